// round 3
// baseline (speedup 1.0000x reference)
#include <cuda_runtime.h>
#include <cstdint>

#define Dm   192
#define DIN  384
#define NSz  16
#define DTRz 12
#define KC   4
#define CIN  96
#define Bz   2
#define L0z  3136
#define L1z  784
#define BL0  (Bz*L0z)

// ---------------- static scratch (no allocs allowed) ----------------
__device__ float g_x   [Bz*Dm*L0z];      // current activation (B, D, L) channel-major
__device__ float g_pool[Bz*Dm*L1z];      // maxpooled
__device__ float g_h   [BL0*Dm];         // layernorm output (B, L, D)
__device__ float g_xz  [BL0*2*DIN];      // in-proj output (B, L, 768)
__device__ float g_xi  [BL0*DIN];        // conv+silu output (B, L, 384)
__device__ float g_proj[BL0*44];         // x-proj (B, L, 44)
__device__ float g_dt  [BL0*DIN];        // softplus(dt) (B, L, 384)
__device__ float g_y   [BL0*DIN];        // scan output gated (B, L, 384)
__device__ float g_blk [BL0*Dm];         // out-proj output (B, L, 192)

// ---------------- 1x1 conv (96->192) + BatchNorm ----------------
__global__ void proj_bn_kernel(const float* __restrict__ x, const float* __restrict__ w,
                               const float* __restrict__ pb, const float* __restrict__ bg,
                               const float* __restrict__ bb, const float* __restrict__ bm,
                               const float* __restrict__ bv, float* __restrict__ out) {
    __shared__ float sw[CIN];
    int b = blockIdx.x / Dm;
    int o = blockIdx.x % Dm;
    for (int c = threadIdx.x; c < CIN; c += blockDim.x) sw[c] = w[o*CIN + c];
    __syncthreads();
    float scale = rsqrtf(bv[o] + 1e-5f) * bg[o];
    float shift = bb[o] - bm[o] * scale;
    const float* xb = x + (size_t)b*CIN*L0z;
    float* ob = out + ((size_t)b*Dm + o)*L0z;
    for (int hw = threadIdx.x; hw < L0z; hw += blockDim.x) {
        float acc = pb[o];
        #pragma unroll 8
        for (int c = 0; c < CIN; c++) acc += sw[c] * xb[(size_t)c*L0z + hw];
        ob[hw] = acc*scale + shift;
    }
}

// ---------------- transpose + LayerNorm over D=192 ----------------
// xin: (B, D, L)  ->  hout: (B, L, D) normalized
__global__ void ln_kernel(const float* __restrict__ xin, const float* __restrict__ g,
                          const float* __restrict__ bb, float* __restrict__ hout, int L) {
    __shared__ float s[32][Dm + 1];
    int tiles = (L + 31) / 32;
    int b  = blockIdx.x / tiles;
    int l0 = (blockIdx.x % tiles) * 32;
    for (int idx = threadIdx.x; idx < 32*Dm; idx += 256) {
        int ll = idx & 31;
        int c  = idx >> 5;
        int l  = l0 + ll;
        s[ll][c] = (l < L) ? xin[((size_t)b*Dm + c)*L + l] : 0.f;
    }
    __syncthreads();
    int warp = threadIdx.x >> 5, lane = threadIdx.x & 31;
    for (int r = 0; r < 4; r++) {
        int ll = warp + r*8;
        int l = l0 + ll;
        if (l >= L) continue;           // uniform within warp
        float v[6]; float sum = 0.f, sq = 0.f;
        #pragma unroll
        for (int j = 0; j < 6; j++) { v[j] = s[ll][lane + 32*j]; sum += v[j]; sq += v[j]*v[j]; }
        #pragma unroll
        for (int o = 16; o > 0; o >>= 1) {
            sum += __shfl_xor_sync(0xffffffffu, sum, o);
            sq  += __shfl_xor_sync(0xffffffffu, sq,  o);
        }
        float mu = sum * (1.f/Dm);
        float var = sq * (1.f/Dm) - mu*mu;
        float rs = rsqrtf(var + 1e-5f);
        float* orow = hout + ((size_t)b*L + l)*Dm;
        #pragma unroll
        for (int j = 0; j < 6; j++) {
            int c = lane + 32*j;
            orow[c] = (v[j]-mu)*rs*g[c] + bb[c];
        }
    }
}

// ---------------- generic tiled SGEMM: C = A(M,K) * B(N,K)^T + bias, opt softplus ----------------
__global__ void sgemm_abT(const float* __restrict__ A, int lda,
                          const float* __restrict__ Bm, int ldb,
                          const float* __restrict__ bias,
                          float* __restrict__ C, int ldc,
                          int M, int N, int K, int act) {
    __shared__ float As[16][65];
    __shared__ float Bs[16][65];
    int bm = blockIdx.y * 64, bn = blockIdx.x * 64;
    int tid = threadIdx.x;
    int tx = tid & 15, ty = tid >> 4;
    float acc[4][4] = {};
    for (int k0 = 0; k0 < K; k0 += 16) {
        int r  = tid >> 2;
        int kb = (tid & 3) * 4;
        #pragma unroll
        for (int v = 0; v < 4; v++) {
            int kk = kb + v, gk = k0 + kk;
            int gm = bm + r;
            As[kk][r] = (gm < M && gk < K) ? A[(size_t)gm*lda + gk] : 0.f;
            int gn = bn + r;
            Bs[kk][r] = (gn < N && gk < K) ? Bm[(size_t)gn*ldb + gk] : 0.f;
        }
        __syncthreads();
        #pragma unroll
        for (int kk = 0; kk < 16; kk++) {
            float a[4], bvv[4];
            #pragma unroll
            for (int i = 0; i < 4; i++) a[i] = As[kk][ty*4 + i];
            #pragma unroll
            for (int j = 0; j < 4; j++) bvv[j] = Bs[kk][tx*4 + j];
            #pragma unroll
            for (int i = 0; i < 4; i++)
                #pragma unroll
                for (int j = 0; j < 4; j++) acc[i][j] = fmaf(a[i], bvv[j], acc[i][j]);
        }
        __syncthreads();
    }
    #pragma unroll
    for (int i = 0; i < 4; i++) {
        int gm = bm + ty*4 + i;
        if (gm >= M) continue;
        #pragma unroll
        for (int j = 0; j < 4; j++) {
            int gn = bn + tx*4 + j;
            if (gn >= N) continue;
            float v = acc[i][j] + (bias ? bias[gn] : 0.f);
            if (act == 1) v = (v > 20.f) ? v : log1pf(__expf(v));   // softplus
            C[(size_t)gm*ldc + gn] = v;
        }
    }
}

// ---------------- causal depthwise conv (K=4) + SiLU ----------------
__global__ void conv_silu(const float* __restrict__ xz, const float* __restrict__ w,
                          const float* __restrict__ cb, float* __restrict__ xo, int L) {
    int i = blockIdx.x*blockDim.x + threadIdx.x;
    int total = Bz*L*DIN;
    if (i >= total) return;
    int e = i % DIN;
    int l = (i / DIN) % L;
    int b = i / (DIN * L);
    float acc = cb[e];
    #pragma unroll
    for (int k = 0; k < KC; k++) {
        int ls = l - (KC-1) + k;
        if (ls >= 0) acc += xz[((size_t)b*L + ls)*(2*DIN) + e] * w[e*KC + k];
    }
    float sg = 1.f / (1.f + __expf(-acc));
    xo[(size_t)i] = acc * sg;
}

// ---------------- selective scan: one thread per (e,n), 16-lane reduce ----------------
__global__ void scan_kernel(const float* __restrict__ dt, const float* __restrict__ xi,
                            const float* __restrict__ proj, const float* __restrict__ xz,
                            const float* __restrict__ A_log, const float* __restrict__ Dskip,
                            float* __restrict__ y, int L) {
    int b  = blockIdx.x / (DIN/8);
    int ch = blockIdx.x % (DIN/8);
    int e = ch*8 + (threadIdx.x >> 4);
    int n = threadIdx.x & 15;
    float A  = -expf(A_log[e*NSz + n]);
    float Dk = Dskip[e];
    float h = 0.f;
    size_t base_de = (size_t)b*L*DIN + e;
    size_t base_p  = (size_t)b*L*44;
    size_t base_z  = (size_t)b*L*(2*DIN) + DIN + e;
    for (int l = 0; l < L; l++) {
        float tdt = dt[base_de + (size_t)l*DIN];
        float txi = xi[base_de + (size_t)l*DIN];
        float tB  = proj[base_p + (size_t)l*44 + DTRz + n];
        float tC  = proj[base_p + (size_t)l*44 + DTRz + NSz + n];
        float dA = __expf(tdt * A);
        h = fmaf(dA, h, tdt*txi*tB);
        float p = h * tC;
        p += __shfl_xor_sync(0xffffffffu, p, 8);
        p += __shfl_xor_sync(0xffffffffu, p, 4);
        p += __shfl_xor_sync(0xffffffffu, p, 2);
        p += __shfl_xor_sync(0xffffffffu, p, 1);
        if (n == 0) {
            float zv = xz[base_z + (size_t)l*(2*DIN)];
            float sz = zv / (1.f + __expf(-zv));
            y[base_de + (size_t)l*DIN] = (p + Dk*txi) * sz;
        }
    }
}

// ---------------- transpose (B,L,192)->(B,192,L), add or assign ----------------
__global__ void add_transpose(const float* __restrict__ src, float* __restrict__ dst,
                              int L, int mode) {
    __shared__ float s[32][33];
    int b  = blockIdx.z;
    int d0 = blockIdx.y * 32;
    int l0 = blockIdx.x * 32;
    int tx = threadIdx.x, ty = threadIdx.y;
    #pragma unroll
    for (int i = 0; i < 32; i += 8) {
        int l = l0 + ty + i, d = d0 + tx;
        if (l < L) s[ty+i][tx] = src[((size_t)b*L + l)*Dm + d];
    }
    __syncthreads();
    #pragma unroll
    for (int i = 0; i < 32; i += 8) {
        int d = d0 + ty + i, l = l0 + tx;
        if (l < L) {
            size_t o = ((size_t)b*Dm + d)*L + l;
            float v = s[tx][ty+i];
            if (mode) dst[o] = v; else dst[o] += v;
        }
    }
}

// ---------------- 2x2 maxpool ----------------
__global__ void maxpool2(const float* __restrict__ in, float* __restrict__ out) {
    int i = blockIdx.x*blockDim.x + threadIdx.x;
    if (i >= Bz*Dm*28*28) return;
    int wo = i % 28, ho = (i/28) % 28;
    int d = (i/784) % Dm, b = i/(784*Dm);
    const float* p = in + (((size_t)(b*Dm + d)*56 + 2*ho)*56 + 2*wo);
    out[i] = fmaxf(fmaxf(p[0], p[1]), fmaxf(p[56], p[57]));
}

// ---------------- host ----------------
extern "C" void kernel_launch(void* const* d_in, const int* in_sizes, int n_in,
                              void* d_out, int out_size) {
    const float* x      = (const float*)d_in[0];
    const float* proj_w = (const float*)d_in[1];
    const float* proj_b = (const float*)d_in[2];
    const float* bn_g   = (const float*)d_in[3];
    const float* bn_b   = (const float*)d_in[4];
    const float* bn_mean= (const float*)d_in[5];
    const float* bn_var = (const float*)d_in[6];
    const float* ln_g   = (const float*)d_in[7];
    const float* ln_b   = (const float*)d_in[8];
    const float* Win    = (const float*)d_in[9];
    const float* b_in   = (const float*)d_in[10];
    const float* conv_w = (const float*)d_in[11];
    const float* conv_b = (const float*)d_in[12];
    const float* Wx     = (const float*)d_in[13];
    const float* Wdt    = (const float*)d_in[14];
    const float* bdt    = (const float*)d_in[15];
    const float* A_log  = (const float*)d_in[16];
    const float* Dskip  = (const float*)d_in[17];
    const float* Wout   = (const float*)d_in[18];
    const float* bout   = (const float*)d_in[19];
    float* out = (float*)d_out;

    float *px, *ppool, *ph, *pxz, *pxi, *pproj, *pdt, *py, *pblk;
    cudaGetSymbolAddress((void**)&px,    g_x);
    cudaGetSymbolAddress((void**)&ppool, g_pool);
    cudaGetSymbolAddress((void**)&ph,    g_h);
    cudaGetSymbolAddress((void**)&pxz,   g_xz);
    cudaGetSymbolAddress((void**)&pxi,   g_xi);
    cudaGetSymbolAddress((void**)&pproj, g_proj);
    cudaGetSymbolAddress((void**)&pdt,   g_dt);
    cudaGetSymbolAddress((void**)&py,    g_y);
    cudaGetSymbolAddress((void**)&pblk,  g_blk);

    // stem: 1x1 conv + BN
    proj_bn_kernel<<<Bz*Dm, 256>>>(x, proj_w, proj_b, bn_g, bn_b, bn_mean, bn_var, px);

    auto run_block = [&](int i, const float* xin, int L, float* dst, int mode) {
        int BLc = Bz * L;
        int tiles = (L + 31) / 32;
        ln_kernel<<<Bz*tiles, 256>>>(xin, ln_g + i*Dm, ln_b + i*Dm, ph, L);

        dim3 gxz((2*DIN + 63)/64, (BLc + 63)/64);
        sgemm_abT<<<gxz, 256>>>(ph, Dm, Win + (size_t)i*2*DIN*Dm, Dm,
                                b_in + i*2*DIN, pxz, 2*DIN, BLc, 2*DIN, Dm, 0);

        int tot = BLc * DIN;
        conv_silu<<<(tot + 255)/256, 256>>>(pxz, conv_w + i*DIN*KC, conv_b + i*DIN, pxi, L);

        dim3 gpr((44 + 63)/64, (BLc + 63)/64);
        sgemm_abT<<<gpr, 256>>>(pxi, DIN, Wx + (size_t)i*44*DIN, DIN,
                                nullptr, pproj, 44, BLc, 44, DIN, 0);

        dim3 gdt((DIN + 63)/64, (BLc + 63)/64);
        sgemm_abT<<<gdt, 256>>>(pproj, 44, Wdt + (size_t)i*DIN*DTRz, DTRz,
                                bdt + i*DIN, pdt, DIN, BLc, DIN, DTRz, 1);

        scan_kernel<<<Bz*(DIN/8), 128>>>(pdt, pxi, pproj, pxz,
                                         A_log + (size_t)i*DIN*NSz, Dskip + i*DIN, py, L);

        dim3 gou((Dm + 63)/64, (BLc + 63)/64);
        sgemm_abT<<<gou, 256>>>(py, DIN, Wout + (size_t)i*Dm*DIN, DIN,
                                bout + i*Dm, pblk, Dm, BLc, Dm, DIN, 0);

        dim3 gtr((L + 31)/32, Dm/32, Bz);
        add_transpose<<<gtr, dim3(32, 8)>>>(pblk, dst, L, mode);
    };

    run_block(0, px, L0z, px, 0);      // x = x + blk0(x)
    run_block(1, px, L0z, px, 0);      // x = x + blk1(x)

    // skip = x  (second output region)
    cudaMemcpyAsync(out + (size_t)Bz*Dm*L1z, px, sizeof(float)*(size_t)Bz*Dm*L0z,
                    cudaMemcpyDeviceToDevice);

    maxpool2<<<(Bz*Dm*784 + 255)/256, 256>>>(px, ppool);
    run_block(2, ppool, L1z, out, 1);  // x_final = blk2(pool(x)) -> first output region
}

// round 5
// speedup vs baseline: 6.5845x; 6.5845x over previous
#include <cuda_runtime.h>
#include <cstdint>

#define Dm   192
#define DIN  384
#define NSz  16
#define DTRz 12
#define KC   4
#define CIN  96
#define Bz   2
#define L0z  3136
#define L1z  784
#define BL0  (Bz*L0z)
#define NCHMAX 49

// ---------------- static scratch (no allocs allowed) ----------------
__device__ float g_x   [Bz*Dm*L0z];      // current activation (B, D, L) channel-major
__device__ float g_pool[Bz*Dm*L1z];      // maxpooled
__device__ float g_h   [BL0*Dm];         // layernorm output (B, L, D)
__device__ float g_xz  [BL0*2*DIN];      // in-proj output (B, L, 768)
__device__ float g_xi  [BL0*DIN];        // conv+silu output (B, L, 384)
__device__ float g_proj[BL0*44];         // x-proj (B, L, 44)
__device__ float g_dt  [BL0*DIN];        // softplus(dt) (B, L, 384)
__device__ float g_y   [BL0*DIN];        // scan output gated (B, L, 384)
__device__ float g_blk [BL0*Dm];         // out-proj output (B, L, 192)
__device__ float g_Pc  [Bz*NCHMAX*DIN*NSz];  // per-chunk decay product
__device__ float g_Hc  [Bz*NCHMAX*DIN*NSz];  // per-chunk local end-state
__device__ float g_Hin [Bz*NCHMAX*DIN*NSz];  // per-chunk incoming state

// ---------------- 1x1 conv (96->192) + BatchNorm, 8 outs/block, hw-quartered --------
__global__ void proj_bn_kernel(const float* __restrict__ x, const float* __restrict__ w,
                               const float* __restrict__ pb, const float* __restrict__ bg,
                               const float* __restrict__ bb, const float* __restrict__ bm,
                               const float* __restrict__ bv, float* __restrict__ out) {
    __shared__ float sw[8][CIN];
    __shared__ float sscale[8], sshift[8];
    int hq   = blockIdx.x & 3;
    int rest = blockIdx.x >> 2;
    int ogi  = rest % (Dm/8);
    int b    = rest / (Dm/8);
    int og   = ogi * 8;
    for (int idx = threadIdx.x; idx < 8*CIN; idx += 256) {
        int j = idx / CIN, c = idx % CIN;
        sw[j][c] = w[(og + j)*CIN + c];
    }
    if (threadIdx.x < 8) {
        int o = og + threadIdx.x;
        float sc = rsqrtf(bv[o] + 1e-5f) * bg[o];
        sscale[threadIdx.x] = sc;
        sshift[threadIdx.x] = bb[o] - bm[o]*sc + pb[o]*sc;
    }
    __syncthreads();
    const float* xb = x + (size_t)b*CIN*L0z;
    int hw0 = hq * (L0z/4), hw1 = hw0 + (L0z/4);
    for (int hw = hw0 + threadIdx.x; hw < hw1; hw += 256) {
        float acc[8] = {};
        #pragma unroll 4
        for (int c = 0; c < CIN; c++) {
            float xv = xb[(size_t)c*L0z + hw];
            #pragma unroll
            for (int j = 0; j < 8; j++) acc[j] = fmaf(sw[j][c], xv, acc[j]);
        }
        #pragma unroll
        for (int j = 0; j < 8; j++)
            out[((size_t)b*Dm + og + j)*L0z + hw] = acc[j]*sscale[j] + sshift[j];
    }
}

// ---------------- transpose + LayerNorm over D=192 ----------------
__global__ void ln_kernel(const float* __restrict__ xin, const float* __restrict__ g,
                          const float* __restrict__ bb, float* __restrict__ hout, int L) {
    __shared__ float s[32][Dm + 1];
    int tiles = (L + 31) / 32;
    int b  = blockIdx.x / tiles;
    int l0 = (blockIdx.x % tiles) * 32;
    for (int idx = threadIdx.x; idx < 32*Dm; idx += 256) {
        int ll = idx & 31;
        int c  = idx >> 5;
        int l  = l0 + ll;
        s[ll][c] = (l < L) ? xin[((size_t)b*Dm + c)*L + l] : 0.f;
    }
    __syncthreads();
    int warp = threadIdx.x >> 5, lane = threadIdx.x & 31;
    for (int r = 0; r < 4; r++) {
        int ll = warp + r*8;
        int l = l0 + ll;
        if (l >= L) continue;
        float v[6]; float sum = 0.f, sq = 0.f;
        #pragma unroll
        for (int j = 0; j < 6; j++) { v[j] = s[ll][lane + 32*j]; sum += v[j]; sq += v[j]*v[j]; }
        #pragma unroll
        for (int o = 16; o > 0; o >>= 1) {
            sum += __shfl_xor_sync(0xffffffffu, sum, o);
            sq  += __shfl_xor_sync(0xffffffffu, sq,  o);
        }
        float mu = sum * (1.f/Dm);
        float var = sq * (1.f/Dm) - mu*mu;
        float rs = rsqrtf(var + 1e-5f);
        float* orow = hout + ((size_t)b*L + l)*Dm;
        #pragma unroll
        for (int j = 0; j < 6; j++) {
            int c = lane + 32*j;
            orow[c] = (v[j]-mu)*rs*g[c] + bb[c];
        }
    }
}

// ---------------- SGEMM: C = A(M,K) * B(N,K)^T + bias, opt softplus ----------------
// 128x64 tile, BK=16, 256 threads, 8x4 microtile, vectorized smem reads.
// Requires K % 4 == 0, lda/ldb/ldc % 4 == 0 (true for all call sites).
__global__ __launch_bounds__(256) void sgemm128(
        const float* __restrict__ A, int lda,
        const float* __restrict__ B, int ldb,
        const float* __restrict__ bias,
        float* __restrict__ C, int ldc,
        int M, int N, int K, int act) {
    __shared__ float As[16][128];
    __shared__ float Bs[16][64];
    int bm = blockIdx.y * 128, bn = blockIdx.x * 64;
    int tid  = threadIdx.x;
    int tx   = tid & 15;          // col group (x4)
    int ty   = tid >> 4;          // row group (x8)
    int arow = tid >> 2;          // 0..63
    int kvec = (tid & 3) * 4;     // 0,4,8,12
    float acc[8][4] = {};

    for (int k0 = 0; k0 < K; k0 += 16) {
        // stage A: rows arow, arow+64 (transposed into As[k][m])
        #pragma unroll
        for (int hh = 0; hh < 2; hh++) {
            int r  = arow + hh*64;
            int gm = bm + r;
            float4 v = make_float4(0.f,0.f,0.f,0.f);
            if (gm < M && (k0 + kvec) < K)
                v = *(const float4*)(A + (size_t)gm*lda + k0 + kvec);
            As[kvec+0][r] = v.x; As[kvec+1][r] = v.y;
            As[kvec+2][r] = v.z; As[kvec+3][r] = v.w;
        }
        // stage B
        {
            int gn = bn + arow;
            float4 v = make_float4(0.f,0.f,0.f,0.f);
            if (gn < N && (k0 + kvec) < K)
                v = *(const float4*)(B + (size_t)gn*ldb + k0 + kvec);
            Bs[kvec+0][arow] = v.x; Bs[kvec+1][arow] = v.y;
            Bs[kvec+2][arow] = v.z; Bs[kvec+3][arow] = v.w;
        }
        __syncthreads();
        #pragma unroll
        for (int kk = 0; kk < 16; kk++) {
            float a[8], bv[4];
            *(float4*)(a)     = *(const float4*)(&As[kk][ty*8]);
            *(float4*)(a + 4) = *(const float4*)(&As[kk][ty*8 + 4]);
            *(float4*)(bv)    = *(const float4*)(&Bs[kk][tx*4]);
            #pragma unroll
            for (int i = 0; i < 8; i++)
                #pragma unroll
                for (int j = 0; j < 4; j++)
                    acc[i][j] = fmaf(a[i], bv[j], acc[i][j]);
        }
        __syncthreads();
    }

    int gn = bn + tx*4;
    if (gn >= N) return;
    float bsv[4] = {0.f,0.f,0.f,0.f};
    if (bias) { *(float4*)bsv = *(const float4*)(bias + gn); }
    #pragma unroll
    for (int i = 0; i < 8; i++) {
        int gm = bm + ty*8 + i;
        if (gm >= M) continue;
        float4 v;
        v.x = acc[i][0] + bsv[0];
        v.y = acc[i][1] + bsv[1];
        v.z = acc[i][2] + bsv[2];
        v.w = acc[i][3] + bsv[3];
        if (act == 1) {
            v.x = (v.x > 20.f) ? v.x : log1pf(__expf(v.x));
            v.y = (v.y > 20.f) ? v.y : log1pf(__expf(v.y));
            v.z = (v.z > 20.f) ? v.z : log1pf(__expf(v.z));
            v.w = (v.w > 20.f) ? v.w : log1pf(__expf(v.w));
        }
        *(float4*)(C + (size_t)gm*ldc + gn) = v;
    }
}

// ---------------- causal depthwise conv (K=4) + SiLU ----------------
// one block per (b,l), 384 threads (= DIN)
__global__ void conv_silu(const float* __restrict__ xz, const float* __restrict__ w,
                          const float* __restrict__ cb, float* __restrict__ xo, int L) {
    int bl = blockIdx.x;
    int l = bl % L, b = bl / L;
    int e = threadIdx.x;
    float4 wv = *(const float4*)(w + e*4);
    float acc = cb[e];
    const float* base = xz + (size_t)b*L*(2*DIN) + e;
    if (l >= 3) {
        acc = fmaf(base[(size_t)(l-3)*(2*DIN)], wv.x, acc);
        acc = fmaf(base[(size_t)(l-2)*(2*DIN)], wv.y, acc);
        acc = fmaf(base[(size_t)(l-1)*(2*DIN)], wv.z, acc);
        acc = fmaf(base[(size_t)(l  )*(2*DIN)], wv.w, acc);
    } else {
        float wk[4] = {wv.x, wv.y, wv.z, wv.w};
        #pragma unroll
        for (int k = 0; k < KC; k++) {
            int ls = l - (KC-1) + k;
            if (ls >= 0) acc = fmaf(base[(size_t)ls*(2*DIN)], wk[k], acc);
        }
    }
    float sg = 1.f / (1.f + __expf(-acc));
    xo[(size_t)bl*DIN + e] = acc * sg;
}

// ---------------- chunked selective scan ----------------
// pass 1: per-chunk local scan (h from 0) + decay product
__global__ void scan_chunk_local(const float* __restrict__ dt, const float* __restrict__ xi,
                                 const float* __restrict__ proj, const float* __restrict__ A_log,
                                 float* __restrict__ Pc, float* __restrict__ Hc,
                                 int L, int NCH) {
    int b  = blockIdx.x / (DIN/8);
    int ch = blockIdx.x % (DIN/8);
    int chunk = blockIdx.y;
    int e = ch*8 + (threadIdx.x >> 4);
    int n = threadIdx.x & 15;
    float A = -expf(A_log[e*NSz + n]);
    float h = 0.f, P = 1.f;
    int l0 = chunk*64;
    int lend = min(l0 + 64, L);
    size_t base_de = (size_t)b*L*DIN + e;
    size_t base_p  = (size_t)b*L*44 + DTRz + n;
    for (int l = l0; l < lend; l++) {
        float tdt = dt[base_de + (size_t)l*DIN];
        float txi = xi[base_de + (size_t)l*DIN];
        float tB  = proj[base_p + (size_t)l*44];
        float dA = __expf(tdt * A);
        h = fmaf(dA, h, tdt*txi*tB);
        P *= dA;
    }
    size_t idx = ((size_t)(b*NCH + chunk)*DIN + e)*NSz + n;
    Pc[idx] = P;
    Hc[idx] = h;
}

// pass 2: sequential prefix over chunk summaries -> incoming state per chunk
__global__ void scan_chunk_prefix(const float* __restrict__ Pc, const float* __restrict__ Hc,
                                  float* __restrict__ Hin, int NCH) {
    int i = blockIdx.x*blockDim.x + threadIdx.x;   // 0 .. Bz*DIN*NSz-1
    int b = i / (DIN*NSz);
    int inner = i % (DIN*NSz);
    float h = 0.f;
    for (int c = 0; c < NCH; c++) {
        size_t idx = (size_t)(b*NCH + c)*(DIN*NSz) + inner;
        Hin[idx] = h;
        h = fmaf(Pc[idx], h, Hc[idx]);
    }
}

// pass 3: recompute chunk with correct incoming state, emit gated y
__global__ void scan_chunk_final(const float* __restrict__ dt, const float* __restrict__ xi,
                                 const float* __restrict__ proj, const float* __restrict__ xz,
                                 const float* __restrict__ A_log, const float* __restrict__ Dskip,
                                 const float* __restrict__ Hin, float* __restrict__ y,
                                 int L, int NCH) {
    int b  = blockIdx.x / (DIN/8);
    int ch = blockIdx.x % (DIN/8);
    int chunk = blockIdx.y;
    int e = ch*8 + (threadIdx.x >> 4);
    int n = threadIdx.x & 15;
    float A  = -expf(A_log[e*NSz + n]);
    float Dk = Dskip[e];
    size_t sidx = ((size_t)(b*NCH + chunk)*DIN + e)*NSz + n;
    float h = Hin[sidx];
    int l0 = chunk*64;
    int lend = min(l0 + 64, L);
    size_t base_de = (size_t)b*L*DIN + e;
    size_t base_p  = (size_t)b*L*44;
    size_t base_z  = (size_t)b*L*(2*DIN) + DIN + e;
    for (int l = l0; l < lend; l++) {
        float tdt = dt[base_de + (size_t)l*DIN];
        float txi = xi[base_de + (size_t)l*DIN];
        float tB  = proj[base_p + (size_t)l*44 + DTRz + n];
        float tC  = proj[base_p + (size_t)l*44 + DTRz + NSz + n];
        float dA = __expf(tdt * A);
        h = fmaf(dA, h, tdt*txi*tB);
        float p = h * tC;
        p += __shfl_xor_sync(0xffffffffu, p, 8);
        p += __shfl_xor_sync(0xffffffffu, p, 4);
        p += __shfl_xor_sync(0xffffffffu, p, 2);
        p += __shfl_xor_sync(0xffffffffu, p, 1);
        if (n == 0) {
            float zv = xz[base_z + (size_t)l*(2*DIN)];
            float sz = zv / (1.f + __expf(-zv));
            y[base_de + (size_t)l*DIN] = (p + Dk*txi) * sz;
        }
    }
}

// ---------------- transpose (B,L,192)->(B,192,L), add or assign ----------------
__global__ void add_transpose(const float* __restrict__ src, float* __restrict__ dst,
                              int L, int mode) {
    __shared__ float s[32][33];
    int b  = blockIdx.z;
    int d0 = blockIdx.y * 32;
    int l0 = blockIdx.x * 32;
    int tx = threadIdx.x, ty = threadIdx.y;
    #pragma unroll
    for (int i = 0; i < 32; i += 8) {
        int l = l0 + ty + i, d = d0 + tx;
        if (l < L) s[ty+i][tx] = src[((size_t)b*L + l)*Dm + d];
    }
    __syncthreads();
    #pragma unroll
    for (int i = 0; i < 32; i += 8) {
        int d = d0 + ty + i, l = l0 + tx;
        if (l < L) {
            size_t o = ((size_t)b*Dm + d)*L + l;
            float v = s[tx][ty+i];
            if (mode) dst[o] = v; else dst[o] += v;
        }
    }
}

// ---------------- 2x2 maxpool ----------------
__global__ void maxpool2(const float* __restrict__ in, float* __restrict__ out) {
    int i = blockIdx.x*blockDim.x + threadIdx.x;
    if (i >= Bz*Dm*28*28) return;
    int wo = i % 28, ho = (i/28) % 28;
    int d = (i/784) % Dm, b = i/(784*Dm);
    const float* p = in + (((size_t)(b*Dm + d)*56 + 2*ho)*56 + 2*wo);
    out[i] = fmaxf(fmaxf(p[0], p[1]), fmaxf(p[56], p[57]));
}

// ---------------- host ----------------
extern "C" void kernel_launch(void* const* d_in, const int* in_sizes, int n_in,
                              void* d_out, int out_size) {
    const float* x      = (const float*)d_in[0];
    const float* proj_w = (const float*)d_in[1];
    const float* proj_b = (const float*)d_in[2];
    const float* bn_g   = (const float*)d_in[3];
    const float* bn_b   = (const float*)d_in[4];
    const float* bn_mean= (const float*)d_in[5];
    const float* bn_var = (const float*)d_in[6];
    const float* ln_g   = (const float*)d_in[7];
    const float* ln_b   = (const float*)d_in[8];
    const float* Win    = (const float*)d_in[9];
    const float* b_in   = (const float*)d_in[10];
    const float* conv_w = (const float*)d_in[11];
    const float* conv_b = (const float*)d_in[12];
    const float* Wx     = (const float*)d_in[13];
    const float* Wdt    = (const float*)d_in[14];
    const float* bdt    = (const float*)d_in[15];
    const float* A_log  = (const float*)d_in[16];
    const float* Dskip  = (const float*)d_in[17];
    const float* Wout   = (const float*)d_in[18];
    const float* bout   = (const float*)d_in[19];
    float* out = (float*)d_out;

    float *px, *ppool, *ph, *pxz, *pxi, *pproj, *pdt, *py, *pblk, *pPc, *pHc, *pHin;
    cudaGetSymbolAddress((void**)&px,    g_x);
    cudaGetSymbolAddress((void**)&ppool, g_pool);
    cudaGetSymbolAddress((void**)&ph,    g_h);
    cudaGetSymbolAddress((void**)&pxz,   g_xz);
    cudaGetSymbolAddress((void**)&pxi,   g_xi);
    cudaGetSymbolAddress((void**)&pproj, g_proj);
    cudaGetSymbolAddress((void**)&pdt,   g_dt);
    cudaGetSymbolAddress((void**)&py,    g_y);
    cudaGetSymbolAddress((void**)&pblk,  g_blk);
    cudaGetSymbolAddress((void**)&pPc,   g_Pc);
    cudaGetSymbolAddress((void**)&pHc,   g_Hc);
    cudaGetSymbolAddress((void**)&pHin,  g_Hin);

    // stem: 1x1 conv + BN
    proj_bn_kernel<<<Bz*(Dm/8)*4, 256>>>(x, proj_w, proj_b, bn_g, bn_b, bn_mean, bn_var, px);

    auto run_block = [&](int i, const float* xin, int L, float* dst, int mode) {
        int BLc = Bz * L;
        int NCH = (L + 63) / 64;
        int tiles = (L + 31) / 32;
        ln_kernel<<<Bz*tiles, 256>>>(xin, ln_g + i*Dm, ln_b + i*Dm, ph, L);

        dim3 gxz((2*DIN)/64, (BLc + 127)/128);
        sgemm128<<<gxz, 256>>>(ph, Dm, Win + (size_t)i*2*DIN*Dm, Dm,
                               b_in + i*2*DIN, pxz, 2*DIN, BLc, 2*DIN, Dm, 0);

        conv_silu<<<BLc, DIN>>>(pxz, conv_w + i*DIN*KC, conv_b + i*DIN, pxi, L);

        dim3 gpr((44 + 63)/64, (BLc + 127)/128);
        sgemm128<<<gpr, 256>>>(pxi, DIN, Wx + (size_t)i*44*DIN, DIN,
                               nullptr, pproj, 44, BLc, 44, DIN, 0);

        dim3 gdt(DIN/64, (BLc + 127)/128);
        sgemm128<<<gdt, 256>>>(pproj, 44, Wdt + (size_t)i*DIN*DTRz, DTRz,
                               bdt + i*DIN, pdt, DIN, BLc, DIN, DTRz, 1);

        dim3 gsc(Bz*(DIN/8), NCH);
        scan_chunk_local<<<gsc, 128>>>(pdt, pxi, pproj,
                                       A_log + (size_t)i*DIN*NSz, pPc, pHc, L, NCH);
        scan_chunk_prefix<<<(Bz*DIN*NSz)/256, 256>>>(pPc, pHc, pHin, NCH);
        scan_chunk_final<<<gsc, 128>>>(pdt, pxi, pproj, pxz,
                                       A_log + (size_t)i*DIN*NSz, Dskip + i*DIN,
                                       pHin, py, L, NCH);

        dim3 gou(Dm/64, (BLc + 127)/128);
        sgemm128<<<gou, 256>>>(py, DIN, Wout + (size_t)i*Dm*DIN, DIN,
                               bout + i*Dm, pblk, Dm, BLc, Dm, DIN, 0);

        dim3 gtr((L + 31)/32, Dm/32, Bz);
        add_transpose<<<gtr, dim3(32, 8)>>>(pblk, dst, L, mode);
    };

    run_block(0, px, L0z, px, 0);      // x = x + blk0(x)
    run_block(1, px, L0z, px, 0);      // x = x + blk1(x)

    // skip = x  (second output region)
    cudaMemcpyAsync(out + (size_t)Bz*Dm*L1z, px, sizeof(float)*(size_t)Bz*Dm*L0z,
                    cudaMemcpyDeviceToDevice);

    maxpool2<<<(Bz*Dm*784 + 255)/256, 256>>>(px, ppool);
    run_block(2, ppool, L1z, out, 1);  // x_final = blk2(pool(x)) -> first output region
}

// round 7
// speedup vs baseline: 7.0485x; 1.0705x over previous
#include <cuda_runtime.h>
#include <cstdint>

#define Dm   192
#define DIN  384
#define NSz  16
#define DTRz 12
#define KC   4
#define CIN  96
#define Bz   2
#define L0z  3136
#define L1z  784
#define BL0  (Bz*L0z)
#define NCHMAX 49

// ---------------- static scratch (no allocs allowed) ----------------
__device__ float g_x   [Bz*Dm*L0z];      // current activation (B, D, L) channel-major
__device__ float g_pool[Bz*Dm*L1z];      // maxpooled
__device__ float g_h   [BL0*Dm];         // layernorm output (B, L, D)
__device__ float g_xz  [BL0*2*DIN];      // in-proj output (B, L, 768)
__device__ float g_xi  [BL0*DIN];        // conv+silu output (B, L, 384)
__device__ float g_proj[BL0*44];         // x-proj (B, L, 44)
__device__ float g_dt  [BL0*DIN];        // softplus(dt) (B, L, 384)
__device__ float g_y   [BL0*DIN];        // scan output gated (B, L, 384)
__device__ float g_blk [BL0*Dm];         // out-proj output (B, L, 192)
__device__ float g_Pc  [Bz*NCHMAX*DIN*NSz];  // per-chunk decay product
__device__ float g_Hc  [Bz*NCHMAX*DIN*NSz];  // per-chunk local end-state
__device__ float g_Hin [Bz*NCHMAX*DIN*NSz];  // per-chunk incoming state

__device__ __forceinline__ float tf32_rna(float x) {
    float r;
    asm("cvt.rna.tf32.f32 %0, %1;" : "=f"(r) : "f"(x));
    return r;
}

#define MMA_TF32(c, a, b)                                                     \
    asm volatile("mma.sync.aligned.m16n8k8.row.col.f32.tf32.tf32.f32 "        \
        "{%0,%1,%2,%3},{%4,%5,%6,%7},{%8,%9},{%0,%1,%2,%3};"                  \
        : "+f"((c)[0]), "+f"((c)[1]), "+f"((c)[2]), "+f"((c)[3])              \
        : "r"(__float_as_uint((a)[0])), "r"(__float_as_uint((a)[1])),         \
          "r"(__float_as_uint((a)[2])), "r"(__float_as_uint((a)[3])),         \
          "r"(__float_as_uint((b)[0])), "r"(__float_as_uint((b)[1])))

// ---------------- 1x1 conv (96->192) + BatchNorm, 8 outs/block, hw-quartered --------
__global__ void proj_bn_kernel(const float* __restrict__ x, const float* __restrict__ w,
                               const float* __restrict__ pb, const float* __restrict__ bg,
                               const float* __restrict__ bb, const float* __restrict__ bm,
                               const float* __restrict__ bv, float* __restrict__ out) {
    __shared__ float sw[8][CIN];
    __shared__ float sscale[8], sshift[8];
    int hq   = blockIdx.x & 3;
    int rest = blockIdx.x >> 2;
    int ogi  = rest % (Dm/8);
    int b    = rest / (Dm/8);
    int og   = ogi * 8;
    for (int idx = threadIdx.x; idx < 8*CIN; idx += 256) {
        int j = idx / CIN, c = idx % CIN;
        sw[j][c] = w[(og + j)*CIN + c];
    }
    if (threadIdx.x < 8) {
        int o = og + threadIdx.x;
        float sc = rsqrtf(bv[o] + 1e-5f) * bg[o];
        sscale[threadIdx.x] = sc;
        sshift[threadIdx.x] = bb[o] - bm[o]*sc + pb[o]*sc;
    }
    __syncthreads();
    const float* xb = x + (size_t)b*CIN*L0z;
    int hw0 = hq * (L0z/4), hw1 = hw0 + (L0z/4);
    for (int hw = hw0 + threadIdx.x; hw < hw1; hw += 256) {
        float acc[8] = {};
        #pragma unroll 4
        for (int c = 0; c < CIN; c++) {
            float xv = xb[(size_t)c*L0z + hw];
            #pragma unroll
            for (int j = 0; j < 8; j++) acc[j] = fmaf(sw[j][c], xv, acc[j]);
        }
        #pragma unroll
        for (int j = 0; j < 8; j++)
            out[((size_t)b*Dm + og + j)*L0z + hw] = acc[j]*sscale[j] + sshift[j];
    }
}

// ---------------- transpose + LayerNorm over D=192 ----------------
__global__ void ln_kernel(const float* __restrict__ xin, const float* __restrict__ g,
                          const float* __restrict__ bb, float* __restrict__ hout, int L) {
    __shared__ float s[32][Dm + 1];
    int tiles = (L + 31) / 32;
    int b  = blockIdx.x / tiles;
    int l0 = (blockIdx.x % tiles) * 32;
    for (int idx = threadIdx.x; idx < 32*Dm; idx += 256) {
        int ll = idx & 31;
        int c  = idx >> 5;
        int l  = l0 + ll;
        s[ll][c] = (l < L) ? xin[((size_t)b*Dm + c)*L + l] : 0.f;
    }
    __syncthreads();
    int warp = threadIdx.x >> 5, lane = threadIdx.x & 31;
    for (int r = 0; r < 4; r++) {
        int ll = warp + r*8;
        int l = l0 + ll;
        if (l >= L) continue;
        float v[6]; float sum = 0.f, sq = 0.f;
        #pragma unroll
        for (int j = 0; j < 6; j++) { v[j] = s[ll][lane + 32*j]; sum += v[j]; sq += v[j]*v[j]; }
        #pragma unroll
        for (int o = 16; o > 0; o >>= 1) {
            sum += __shfl_xor_sync(0xffffffffu, sum, o);
            sq  += __shfl_xor_sync(0xffffffffu, sq,  o);
        }
        float mu = sum * (1.f/Dm);
        float var = sq * (1.f/Dm) - mu*mu;
        float rs = rsqrtf(var + 1e-5f);
        float* orow = hout + ((size_t)b*L + l)*Dm;
        #pragma unroll
        for (int j = 0; j < 6; j++) {
            int c = lane + 32*j;
            orow[c] = (v[j]-mu)*rs*g[c] + bb[c];
        }
    }
}

// ---------------- tf32 tensor-core GEMM: C = A(M,K) * B(N,K)^T + bias --------------
// 3-term precision split (AhBh + AlBh + AhBl) -> ~fp32 accuracy.
// 128x64 block tile, 8 warps (4m x 2n), warp tile 32x32, BK=16.
// Requires K%4==0, lda/ldb%4==0, N even, ldc even.
__global__ __launch_bounds__(256) void tgemm(
        const float* __restrict__ A, int lda,
        const float* __restrict__ B, int ldb,
        const float* __restrict__ bias,
        float* __restrict__ C, int ldc,
        int M, int N, int K, int act) {
    __shared__ float Ah[16][136];
    __shared__ float Al[16][136];
    __shared__ float Bh[16][72];
    __shared__ float Bl[16][72];

    int bm = blockIdx.y * 128, bn = blockIdx.x * 64;
    int tid  = threadIdx.x;
    int lane = tid & 31;
    int w    = tid >> 5;
    int m0 = (w >> 1) * 32;
    int n0 = (w & 1) * 32;
    int gq = lane >> 2;      // group id 0..7
    int tq = lane & 3;       // thread-in-group

    int arow = tid >> 2;     // 0..63
    int kvec = (tid & 3) * 4;

    float c[2][4][4] = {};

    for (int k0 = 0; k0 < K; k0 += 16) {
        // ---- stage A (128 rows) split hi/lo ----
        #pragma unroll
        for (int hh = 0; hh < 2; hh++) {
            int r  = arow + hh*64;
            int gm = bm + r;
            float4 v = make_float4(0.f,0.f,0.f,0.f);
            if (gm < M && (k0 + kvec) < K)
                v = *(const float4*)(A + (size_t)gm*lda + k0 + kvec);
            float vv[4] = {v.x, v.y, v.z, v.w};
            #pragma unroll
            for (int t = 0; t < 4; t++) {
                float h = tf32_rna(vv[t]);
                Ah[kvec+t][r] = h;
                Al[kvec+t][r] = tf32_rna(vv[t] - h);
            }
        }
        // ---- stage B (64 rows) split hi/lo ----
        {
            int gn = bn + arow;
            float4 v = make_float4(0.f,0.f,0.f,0.f);
            if (gn < N && (k0 + kvec) < K)
                v = *(const float4*)(B + (size_t)gn*ldb + k0 + kvec);
            float vv[4] = {v.x, v.y, v.z, v.w};
            #pragma unroll
            for (int t = 0; t < 4; t++) {
                float h = tf32_rna(vv[t]);
                Bh[kvec+t][arow] = h;
                Bl[kvec+t][arow] = tf32_rna(vv[t] - h);
            }
        }
        __syncthreads();

        #pragma unroll
        for (int ks = 0; ks < 16; ks += 8) {
            float ah[2][4], al[2][4];
            #pragma unroll
            for (int i = 0; i < 2; i++) {
                int mb = m0 + i*16 + gq;
                ah[i][0] = Ah[ks+tq  ][mb];   ah[i][1] = Ah[ks+tq  ][mb+8];
                ah[i][2] = Ah[ks+tq+4][mb];   ah[i][3] = Ah[ks+tq+4][mb+8];
                al[i][0] = Al[ks+tq  ][mb];   al[i][1] = Al[ks+tq  ][mb+8];
                al[i][2] = Al[ks+tq+4][mb];   al[i][3] = Al[ks+tq+4][mb+8];
            }
            float bh[4][2], bl[4][2];
            #pragma unroll
            for (int j = 0; j < 4; j++) {
                int nb = n0 + j*8 + gq;
                bh[j][0] = Bh[ks+tq  ][nb];   bh[j][1] = Bh[ks+tq+4][nb];
                bl[j][0] = Bl[ks+tq  ][nb];   bl[j][1] = Bl[ks+tq+4][nb];
            }
            #pragma unroll
            for (int i = 0; i < 2; i++)
                #pragma unroll
                for (int j = 0; j < 4; j++) {
                    MMA_TF32(c[i][j], ah[i], bh[j]);
                    MMA_TF32(c[i][j], al[i], bh[j]);
                    MMA_TF32(c[i][j], ah[i], bl[j]);
                }
        }
        __syncthreads();
    }

    // ---- epilogue ----
    #pragma unroll
    for (int i = 0; i < 2; i++) {
        #pragma unroll
        for (int j = 0; j < 4; j++) {
            int n = bn + n0 + j*8 + tq*2;
            if (n >= N) continue;
            float b0 = bias ? bias[n]   : 0.f;
            float b1 = bias ? bias[n+1] : 0.f;
            #pragma unroll
            for (int hh = 0; hh < 2; hh++) {
                int gm = bm + m0 + i*16 + gq + hh*8;
                if (gm >= M) continue;
                float v0 = c[i][j][hh*2 + 0] + b0;
                float v1 = c[i][j][hh*2 + 1] + b1;
                if (act == 1) {
                    v0 = (v0 > 20.f) ? v0 : log1pf(__expf(v0));
                    v1 = (v1 > 20.f) ? v1 : log1pf(__expf(v1));
                }
                float2 st = make_float2(v0, v1);
                *(float2*)(C + (size_t)gm*ldc + n) = st;
            }
        }
    }
}

// ---------------- causal depthwise conv (K=4) + SiLU ----------------
__global__ void conv_silu(const float* __restrict__ xz, const float* __restrict__ w,
                          const float* __restrict__ cb, float* __restrict__ xo, int L) {
    int bl = blockIdx.x;
    int l = bl % L, b = bl / L;
    int e = threadIdx.x;
    float4 wv = *(const float4*)(w + e*4);
    float acc = cb[e];
    const float* base = xz + (size_t)b*L*(2*DIN) + e;
    if (l >= 3) {
        acc = fmaf(base[(size_t)(l-3)*(2*DIN)], wv.x, acc);
        acc = fmaf(base[(size_t)(l-2)*(2*DIN)], wv.y, acc);
        acc = fmaf(base[(size_t)(l-1)*(2*DIN)], wv.z, acc);
        acc = fmaf(base[(size_t)(l  )*(2*DIN)], wv.w, acc);
    } else {
        float wk[4] = {wv.x, wv.y, wv.z, wv.w};
        #pragma unroll
        for (int k = 0; k < KC; k++) {
            int ls = l - (KC-1) + k;
            if (ls >= 0) acc = fmaf(base[(size_t)ls*(2*DIN)], wk[k], acc);
        }
    }
    float sg = 1.f / (1.f + __expf(-acc));
    xo[(size_t)bl*DIN + e] = acc * sg;
}

// ---------------- chunked selective scan ----------------
__global__ void scan_chunk_local(const float* __restrict__ dt, const float* __restrict__ xi,
                                 const float* __restrict__ proj, const float* __restrict__ A_log,
                                 float* __restrict__ Pc, float* __restrict__ Hc,
                                 int L, int NCH) {
    int b  = blockIdx.x / (DIN/8);
    int ch = blockIdx.x % (DIN/8);
    int chunk = blockIdx.y;
    int e = ch*8 + (threadIdx.x >> 4);
    int n = threadIdx.x & 15;
    float A = -expf(A_log[e*NSz + n]);
    float h = 0.f, P = 1.f;
    int l0 = chunk*64;
    int lend = min(l0 + 64, L);
    size_t base_de = (size_t)b*L*DIN + e;
    size_t base_p  = (size_t)b*L*44 + DTRz + n;
    for (int l = l0; l < lend; l++) {
        float tdt = dt[base_de + (size_t)l*DIN];
        float txi = xi[base_de + (size_t)l*DIN];
        float tB  = proj[base_p + (size_t)l*44];
        float dA = __expf(tdt * A);
        h = fmaf(dA, h, tdt*txi*tB);
        P *= dA;
    }
    size_t idx = ((size_t)(b*NCH + chunk)*DIN + e)*NSz + n;
    Pc[idx] = P;
    Hc[idx] = h;
}

__global__ void scan_chunk_prefix(const float* __restrict__ Pc, const float* __restrict__ Hc,
                                  float* __restrict__ Hin, int NCH) {
    int i = blockIdx.x*blockDim.x + threadIdx.x;
    int b = i / (DIN*NSz);
    int inner = i % (DIN*NSz);
    float h = 0.f;
    for (int c = 0; c < NCH; c++) {
        size_t idx = (size_t)(b*NCH + c)*(DIN*NSz) + inner;
        Hin[idx] = h;
        h = fmaf(Pc[idx], h, Hc[idx]);
    }
}

__global__ void scan_chunk_final(const float* __restrict__ dt, const float* __restrict__ xi,
                                 const float* __restrict__ proj, const float* __restrict__ xz,
                                 const float* __restrict__ A_log, const float* __restrict__ Dskip,
                                 const float* __restrict__ Hin, float* __restrict__ y,
                                 int L, int NCH) {
    int b  = blockIdx.x / (DIN/8);
    int ch = blockIdx.x % (DIN/8);
    int chunk = blockIdx.y;
    int e = ch*8 + (threadIdx.x >> 4);
    int n = threadIdx.x & 15;
    float A  = -expf(A_log[e*NSz + n]);
    float Dk = Dskip[e];
    size_t sidx = ((size_t)(b*NCH + chunk)*DIN + e)*NSz + n;
    float h = Hin[sidx];
    int l0 = chunk*64;
    int lend = min(l0 + 64, L);
    size_t base_de = (size_t)b*L*DIN + e;
    size_t base_p  = (size_t)b*L*44;
    size_t base_z  = (size_t)b*L*(2*DIN) + DIN + e;
    for (int l = l0; l < lend; l++) {
        float tdt = dt[base_de + (size_t)l*DIN];
        float txi = xi[base_de + (size_t)l*DIN];
        float tB  = proj[base_p + (size_t)l*44 + DTRz + n];
        float tC  = proj[base_p + (size_t)l*44 + DTRz + NSz + n];
        float dA = __expf(tdt * A);
        h = fmaf(dA, h, tdt*txi*tB);
        float p = h * tC;
        p += __shfl_xor_sync(0xffffffffu, p, 8);
        p += __shfl_xor_sync(0xffffffffu, p, 4);
        p += __shfl_xor_sync(0xffffffffu, p, 2);
        p += __shfl_xor_sync(0xffffffffu, p, 1);
        if (n == 0) {
            float zv = xz[base_z + (size_t)l*(2*DIN)];
            float sz = zv / (1.f + __expf(-zv));
            y[base_de + (size_t)l*DIN] = (p + Dk*txi) * sz;
        }
    }
}

// ---------------- transpose (B,L,192)->(B,192,L), add or assign ----------------
__global__ void add_transpose(const float* __restrict__ src, float* __restrict__ dst,
                              int L, int mode) {
    __shared__ float s[32][33];
    int b  = blockIdx.z;
    int d0 = blockIdx.y * 32;
    int l0 = blockIdx.x * 32;
    int tx = threadIdx.x, ty = threadIdx.y;
    #pragma unroll
    for (int i = 0; i < 32; i += 8) {
        int l = l0 + ty + i, d = d0 + tx;
        if (l < L) s[ty+i][tx] = src[((size_t)b*L + l)*Dm + d];
    }
    __syncthreads();
    #pragma unroll
    for (int i = 0; i < 32; i += 8) {
        int d = d0 + ty + i, l = l0 + tx;
        if (l < L) {
            size_t o = ((size_t)b*Dm + d)*L + l;
            float v = s[tx][ty+i];
            if (mode) dst[o] = v; else dst[o] += v;
        }
    }
}

// ---------------- 2x2 maxpool ----------------
__global__ void maxpool2(const float* __restrict__ in, float* __restrict__ out) {
    int i = blockIdx.x*blockDim.x + threadIdx.x;
    if (i >= Bz*Dm*28*28) return;
    int wo = i % 28, ho = (i/28) % 28;
    int d = (i/784) % Dm, b = i/(784*Dm);
    const float* p = in + (((size_t)(b*Dm + d)*56 + 2*ho)*56 + 2*wo);
    out[i] = fmaxf(fmaxf(p[0], p[1]), fmaxf(p[56], p[57]));
}

// ---------------- host ----------------
extern "C" void kernel_launch(void* const* d_in, const int* in_sizes, int n_in,
                              void* d_out, int out_size) {
    const float* x      = (const float*)d_in[0];
    const float* proj_w = (const float*)d_in[1];
    const float* proj_b = (const float*)d_in[2];
    const float* bn_g   = (const float*)d_in[3];
    const float* bn_b   = (const float*)d_in[4];
    const float* bn_mean= (const float*)d_in[5];
    const float* bn_var = (const float*)d_in[6];
    const float* ln_g   = (const float*)d_in[7];
    const float* ln_b   = (const float*)d_in[8];
    const float* Win    = (const float*)d_in[9];
    const float* b_in   = (const float*)d_in[10];
    const float* conv_w = (const float*)d_in[11];
    const float* conv_b = (const float*)d_in[12];
    const float* Wx     = (const float*)d_in[13];
    const float* Wdt    = (const float*)d_in[14];
    const float* bdt    = (const float*)d_in[15];
    const float* A_log  = (const float*)d_in[16];
    const float* Dskip  = (const float*)d_in[17];
    const float* Wout   = (const float*)d_in[18];
    const float* bout   = (const float*)d_in[19];
    float* out = (float*)d_out;

    float *px, *ppool, *ph, *pxz, *pxi, *pproj, *pdt, *py, *pblk, *pPc, *pHc, *pHin;
    cudaGetSymbolAddress((void**)&px,    g_x);
    cudaGetSymbolAddress((void**)&ppool, g_pool);
    cudaGetSymbolAddress((void**)&ph,    g_h);
    cudaGetSymbolAddress((void**)&pxz,   g_xz);
    cudaGetSymbolAddress((void**)&pxi,   g_xi);
    cudaGetSymbolAddress((void**)&pproj, g_proj);
    cudaGetSymbolAddress((void**)&pdt,   g_dt);
    cudaGetSymbolAddress((void**)&py,    g_y);
    cudaGetSymbolAddress((void**)&pblk,  g_blk);
    cudaGetSymbolAddress((void**)&pPc,   g_Pc);
    cudaGetSymbolAddress((void**)&pHc,   g_Hc);
    cudaGetSymbolAddress((void**)&pHin,  g_Hin);

    // stem: 1x1 conv + BN
    proj_bn_kernel<<<Bz*(Dm/8)*4, 256>>>(x, proj_w, proj_b, bn_g, bn_b, bn_mean, bn_var, px);

    auto run_block = [&](int i, const float* xin, int L, float* dst, int mode) {
        int BLc = Bz * L;
        int NCH = (L + 63) / 64;
        int tiles = (L + 31) / 32;
        ln_kernel<<<Bz*tiles, 256>>>(xin, ln_g + i*Dm, ln_b + i*Dm, ph, L);

        dim3 gxz((2*DIN)/64, (BLc + 127)/128);
        tgemm<<<gxz, 256>>>(ph, Dm, Win + (size_t)i*2*DIN*Dm, Dm,
                            b_in + i*2*DIN, pxz, 2*DIN, BLc, 2*DIN, Dm, 0);

        conv_silu<<<BLc, DIN>>>(pxz, conv_w + i*DIN*KC, conv_b + i*DIN, pxi, L);

        dim3 gpr(1, (BLc + 127)/128);
        tgemm<<<gpr, 256>>>(pxi, DIN, Wx + (size_t)i*44*DIN, DIN,
                            nullptr, pproj, 44, BLc, 44, DIN, 0);

        dim3 gdt(DIN/64, (BLc + 127)/128);
        tgemm<<<gdt, 256>>>(pproj, 44, Wdt + (size_t)i*DIN*DTRz, DTRz,
                            bdt + i*DIN, pdt, DIN, BLc, DIN, DTRz, 1);

        dim3 gsc(Bz*(DIN/8), NCH);
        scan_chunk_local<<<gsc, 128>>>(pdt, pxi, pproj,
                                       A_log + (size_t)i*DIN*NSz, pPc, pHc, L, NCH);
        scan_chunk_prefix<<<(Bz*DIN*NSz)/256, 256>>>(pPc, pHc, pHin, NCH);
        scan_chunk_final<<<gsc, 128>>>(pdt, pxi, pproj, pxz,
                                       A_log + (size_t)i*DIN*NSz, Dskip + i*DIN,
                                       pHin, py, L, NCH);

        dim3 gou(Dm/64, (BLc + 127)/128);
        tgemm<<<gou, 256>>>(py, DIN, Wout + (size_t)i*Dm*DIN, DIN,
                            bout + i*Dm, pblk, Dm, BLc, Dm, DIN, 0);

        dim3 gtr((L + 31)/32, Dm/32, Bz);
        add_transpose<<<gtr, dim3(32, 8)>>>(pblk, dst, L, mode);
    };

    run_block(0, px, L0z, px, 0);      // x = x + blk0(x)
    run_block(1, px, L0z, px, 0);      // x = x + blk1(x)

    // skip = x  (second output region)
    cudaMemcpyAsync(out + (size_t)Bz*Dm*L1z, px, sizeof(float)*(size_t)Bz*Dm*L0z,
                    cudaMemcpyDeviceToDevice);

    maxpool2<<<(Bz*Dm*784 + 255)/256, 256>>>(px, ppool);
    run_block(2, ppool, L1z, out, 1);  // x_final = blk2(pool(x)) -> first output region
}

// round 10
// speedup vs baseline: 9.0666x; 1.2863x over previous
#include <cuda_runtime.h>
#include <cuda_bf16.h>
#include <cstdint>

#define Dm   192
#define DIN  384
#define NSz  16
#define DTRz 12
#define KC   4
#define CIN  96
#define Bz   2
#define L0z  3136
#define L1z  784
#define BL0  (Bz*L0z)
#define NCHMAX 49
#define ASTR 40   // smem row stride in bf16 elements (conflict-free)

// ---------------- static scratch (no allocs allowed) ----------------
__device__ float g_x   [Bz*Dm*L0z];
__device__ float g_pool[Bz*Dm*L1z];
__device__ float g_h   [BL0*Dm];
__device__ float g_xz  [BL0*2*DIN];
__device__ float g_xi  [BL0*DIN];
__device__ float g_proj[BL0*44];
__device__ float g_dt  [BL0*DIN];
__device__ float g_y   [BL0*DIN];
__device__ float g_blk [BL0*Dm];
__device__ float g_Pc  [Bz*NCHMAX*DIN*NSz];
__device__ float g_Hc  [Bz*NCHMAX*DIN*NSz];
__device__ float g_Hin [Bz*NCHMAX*DIN*NSz];

#define MMA_BF16(c, a, b)                                                     \
    asm volatile("mma.sync.aligned.m16n8k16.row.col.f32.bf16.bf16.f32 "       \
        "{%0,%1,%2,%3},{%4,%5,%6,%7},{%8,%9},{%0,%1,%2,%3};"                  \
        : "+f"((c)[0]), "+f"((c)[1]), "+f"((c)[2]), "+f"((c)[3])              \
        : "r"((a)[0]), "r"((a)[1]), "r"((a)[2]), "r"((a)[3]),                 \
          "r"((b)[0]), "r"((b)[1]))

__device__ __forceinline__ uint32_t pack2(__nv_bfloat16 a, __nv_bfloat16 b) {
    return (uint32_t)__bfloat16_as_ushort(a) | ((uint32_t)__bfloat16_as_ushort(b) << 16);
}
__device__ __forceinline__ void split2(float x, float y, uint32_t& hi, uint32_t& lo) {
    __nv_bfloat16 hx = __float2bfloat16(x), hy = __float2bfloat16(y);
    __nv_bfloat16 lx = __float2bfloat16(x - __bfloat162float(hx));
    __nv_bfloat16 ly = __float2bfloat16(y - __bfloat162float(hy));
    hi = pack2(hx, hy);
    lo = pack2(lx, ly);
}

// ============ bf16x3 tensor-core GEMM: C = A(M,K) * B(N,K)^T + bias ============
// block tile 128x64, BK=32, 256 threads, 8 warps (4m x 2n), warp tile 32x32.
// 3-term split: AhBh + AlBh + AhBl -> ~1e-5 accuracy. Requires K%4==0, lda/ldb%4==0.
__global__ __launch_bounds__(256, 2) void bgemm(
        const float* __restrict__ A, int lda,
        const float* __restrict__ B, int ldb,
        const float* __restrict__ bias,
        float* __restrict__ C, int ldc,
        int M, int N, int K, int act) {
    __shared__ __align__(16) uint16_t sAh[128*ASTR];
    __shared__ __align__(16) uint16_t sAl[128*ASTR];
    __shared__ __align__(16) uint16_t sBh[64*ASTR];
    __shared__ __align__(16) uint16_t sBl[64*ASTR];

    int bm = blockIdx.y * 128, bn = blockIdx.x * 64;
    int tid  = threadIdx.x;
    int lane = tid & 31;
    int w    = tid >> 5;
    int m0 = (w >> 1) * 32;
    int n0 = (w & 1) * 32;
    int gq = lane >> 2;
    int tq = lane & 3;

    float c[2][4][4] = {};
    float4 pa[4], pb[2];
    const float4 z4 = make_float4(0.f,0.f,0.f,0.f);

    auto ldA = [&](int k0) {
        #pragma unroll
        for (int it = 0; it < 4; it++) {
            int idx = tid + it*256;
            int r = idx >> 3, q = idx & 7;
            int gm = bm + r, gk = k0 + q*4;
            pa[it] = (gm < M && gk < K) ? *(const float4*)(A + (size_t)gm*lda + gk) : z4;
        }
    };
    auto ldB = [&](int k0) {
        #pragma unroll
        for (int it = 0; it < 2; it++) {
            int idx = tid + it*256;
            int r = idx >> 3, q = idx & 7;
            int gn = bn + r, gk = k0 + q*4;
            pb[it] = (gn < N && gk < K) ? *(const float4*)(B + (size_t)gn*ldb + gk) : z4;
        }
    };
    auto stA = [&]() {
        #pragma unroll
        for (int it = 0; it < 4; it++) {
            int idx = tid + it*256;
            int r = idx >> 3, q = idx & 7;
            uint32_t h0, l0, h1, l1;
            split2(pa[it].x, pa[it].y, h0, l0);
            split2(pa[it].z, pa[it].w, h1, l1);
            int off = r*ASTR + q*4;
            *(uint2*)(sAh + off) = make_uint2(h0, h1);
            *(uint2*)(sAl + off) = make_uint2(l0, l1);
        }
    };
    auto stB = [&]() {
        #pragma unroll
        for (int it = 0; it < 2; it++) {
            int idx = tid + it*256;
            int r = idx >> 3, q = idx & 7;
            uint32_t h0, l0, h1, l1;
            split2(pb[it].x, pb[it].y, h0, l0);
            split2(pb[it].z, pb[it].w, h1, l1);
            int off = r*ASTR + q*4;
            *(uint2*)(sBh + off) = make_uint2(h0, h1);
            *(uint2*)(sBl + off) = make_uint2(l0, l1);
        }
    };

    int nst = (K + 31) / 32;
    ldA(0); ldB(0);
    for (int s = 0; s < nst; s++) {
        stA(); stB();
        __syncthreads();
        if (s + 1 < nst) { ldA((s+1)*32); ldB((s+1)*32); }

        #pragma unroll
        for (int ks = 0; ks < 32; ks += 16) {
            uint32_t ah[2][4], al[2][4], bh[4][2], bl[4][2];
            #pragma unroll
            for (int i = 0; i < 2; i++) {
                int mb = m0 + i*16 + gq;
                int o0 = mb*ASTR + 2*tq + ks;
                int o1 = (mb+8)*ASTR + 2*tq + ks;
                ah[i][0] = *(const uint32_t*)(sAh + o0);
                ah[i][1] = *(const uint32_t*)(sAh + o1);
                ah[i][2] = *(const uint32_t*)(sAh + o0 + 8);
                ah[i][3] = *(const uint32_t*)(sAh + o1 + 8);
                al[i][0] = *(const uint32_t*)(sAl + o0);
                al[i][1] = *(const uint32_t*)(sAl + o1);
                al[i][2] = *(const uint32_t*)(sAl + o0 + 8);
                al[i][3] = *(const uint32_t*)(sAl + o1 + 8);
            }
            #pragma unroll
            for (int j = 0; j < 4; j++) {
                int nb = n0 + j*8 + gq;
                int o = nb*ASTR + 2*tq + ks;
                bh[j][0] = *(const uint32_t*)(sBh + o);
                bh[j][1] = *(const uint32_t*)(sBh + o + 8);
                bl[j][0] = *(const uint32_t*)(sBl + o);
                bl[j][1] = *(const uint32_t*)(sBl + o + 8);
            }
            #pragma unroll
            for (int i = 0; i < 2; i++)
                #pragma unroll
                for (int j = 0; j < 4; j++) {
                    MMA_BF16(c[i][j], ah[i], bh[j]);
                    MMA_BF16(c[i][j], al[i], bh[j]);
                    MMA_BF16(c[i][j], ah[i], bl[j]);
                }
        }
        __syncthreads();
    }

    // ---- epilogue ----
    #pragma unroll
    for (int i = 0; i < 2; i++) {
        #pragma unroll
        for (int j = 0; j < 4; j++) {
            int n = bn + n0 + j*8 + tq*2;
            if (n >= N) continue;
            float b0 = bias ? bias[n]   : 0.f;
            float b1 = bias ? bias[n+1] : 0.f;
            #pragma unroll
            for (int hh = 0; hh < 2; hh++) {
                int gm = bm + m0 + i*16 + gq + hh*8;
                if (gm >= M) continue;
                float v0 = c[i][j][hh*2 + 0] + b0;
                float v1 = c[i][j][hh*2 + 1] + b1;
                if (act == 1) {
                    v0 = (v0 > 20.f) ? v0 : log1pf(__expf(v0));
                    v1 = (v1 > 20.f) ? v1 : log1pf(__expf(v1));
                }
                *(float2*)(C + (size_t)gm*ldc + n) = make_float2(v0, v1);
            }
        }
    }
}

// ---------------- 1x1 conv (96->192) + BatchNorm ----------------
__global__ void proj_bn_kernel(const float* __restrict__ x, const float* __restrict__ w,
                               const float* __restrict__ pb, const float* __restrict__ bg,
                               const float* __restrict__ bb, const float* __restrict__ bm,
                               const float* __restrict__ bv, float* __restrict__ out) {
    __shared__ float sw[8][CIN];
    __shared__ float sscale[8], sshift[8];
    int hq   = blockIdx.x & 3;
    int rest = blockIdx.x >> 2;
    int ogi  = rest % (Dm/8);
    int b    = rest / (Dm/8);
    int og   = ogi * 8;
    for (int idx = threadIdx.x; idx < 8*CIN; idx += 256) {
        int j = idx / CIN, c = idx % CIN;
        sw[j][c] = w[(og + j)*CIN + c];
    }
    if (threadIdx.x < 8) {
        int o = og + threadIdx.x;
        float sc = rsqrtf(bv[o] + 1e-5f) * bg[o];
        sscale[threadIdx.x] = sc;
        sshift[threadIdx.x] = bb[o] - bm[o]*sc + pb[o]*sc;
    }
    __syncthreads();
    const float* xb = x + (size_t)b*CIN*L0z;
    int hw0 = hq * (L0z/4), hw1 = hw0 + (L0z/4);
    for (int hw = hw0 + threadIdx.x; hw < hw1; hw += 256) {
        float acc[8] = {};
        #pragma unroll 4
        for (int c = 0; c < CIN; c++) {
            float xv = xb[(size_t)c*L0z + hw];
            #pragma unroll
            for (int j = 0; j < 8; j++) acc[j] = fmaf(sw[j][c], xv, acc[j]);
        }
        #pragma unroll
        for (int j = 0; j < 8; j++)
            out[((size_t)b*Dm + og + j)*L0z + hw] = acc[j]*sscale[j] + sshift[j];
    }
}

// ---------------- transpose + LayerNorm over D=192 ----------------
__global__ void ln_kernel(const float* __restrict__ xin, const float* __restrict__ g,
                          const float* __restrict__ bb, float* __restrict__ hout, int L) {
    __shared__ float s[32][Dm + 1];
    int tiles = (L + 31) / 32;
    int b  = blockIdx.x / tiles;
    int l0 = (blockIdx.x % tiles) * 32;
    for (int idx = threadIdx.x; idx < 32*Dm; idx += 256) {
        int ll = idx & 31;
        int c  = idx >> 5;
        int l  = l0 + ll;
        s[ll][c] = (l < L) ? xin[((size_t)b*Dm + c)*L + l] : 0.f;
    }
    __syncthreads();
    int warp = threadIdx.x >> 5, lane = threadIdx.x & 31;
    for (int r = 0; r < 4; r++) {
        int ll = warp + r*8;
        int l = l0 + ll;
        if (l >= L) continue;
        float v[6]; float sum = 0.f, sq = 0.f;
        #pragma unroll
        for (int j = 0; j < 6; j++) { v[j] = s[ll][lane + 32*j]; sum += v[j]; sq += v[j]*v[j]; }
        #pragma unroll
        for (int o = 16; o > 0; o >>= 1) {
            sum += __shfl_xor_sync(0xffffffffu, sum, o);
            sq  += __shfl_xor_sync(0xffffffffu, sq,  o);
        }
        float mu = sum * (1.f/Dm);
        float var = sq * (1.f/Dm) - mu*mu;
        float rs = rsqrtf(var + 1e-5f);
        float* orow = hout + ((size_t)b*L + l)*Dm;
        #pragma unroll
        for (int j = 0; j < 6; j++) {
            int c = lane + 32*j;
            orow[c] = (v[j]-mu)*rs*g[c] + bb[c];
        }
    }
}

// ---------------- causal depthwise conv (K=4) + SiLU ----------------
__global__ void conv_silu(const float* __restrict__ xz, const float* __restrict__ w,
                          const float* __restrict__ cb, float* __restrict__ xo, int L) {
    int bl = blockIdx.x;
    int l = bl % L, b = bl / L;
    int e = threadIdx.x;
    float4 wv = *(const float4*)(w + e*4);
    float acc = cb[e];
    const float* base = xz + (size_t)b*L*(2*DIN) + e;
    if (l >= 3) {
        acc = fmaf(base[(size_t)(l-3)*(2*DIN)], wv.x, acc);
        acc = fmaf(base[(size_t)(l-2)*(2*DIN)], wv.y, acc);
        acc = fmaf(base[(size_t)(l-1)*(2*DIN)], wv.z, acc);
        acc = fmaf(base[(size_t)(l  )*(2*DIN)], wv.w, acc);
    } else {
        float wk[4] = {wv.x, wv.y, wv.z, wv.w};
        #pragma unroll
        for (int k = 0; k < KC; k++) {
            int ls = l - (KC-1) + k;
            if (ls >= 0) acc = fmaf(base[(size_t)ls*(2*DIN)], wk[k], acc);
        }
    }
    float sg = 1.f / (1.f + __expf(-acc));
    xo[(size_t)bl*DIN + e] = acc * sg;
}

// ---------------- chunked selective scan ----------------
__global__ void scan_chunk_local(const float* __restrict__ dt, const float* __restrict__ xi,
                                 const float* __restrict__ proj, const float* __restrict__ A_log,
                                 float* __restrict__ Pc, float* __restrict__ Hc,
                                 int L, int NCH) {
    int b  = blockIdx.x / (DIN/8);
    int ch = blockIdx.x % (DIN/8);
    int chunk = blockIdx.y;
    int e = ch*8 + (threadIdx.x >> 4);
    int n = threadIdx.x & 15;
    float A = -expf(A_log[e*NSz + n]);
    float h = 0.f, P = 1.f;
    int l0 = chunk*64;
    int lend = min(l0 + 64, L);
    size_t base_de = (size_t)b*L*DIN + e;
    size_t base_p  = (size_t)b*L*44 + DTRz + n;
    for (int l = l0; l < lend; l++) {
        float tdt = dt[base_de + (size_t)l*DIN];
        float txi = xi[base_de + (size_t)l*DIN];
        float tB  = proj[base_p + (size_t)l*44];
        float dA = __expf(tdt * A);
        h = fmaf(dA, h, tdt*txi*tB);
        P *= dA;
    }
    size_t idx = ((size_t)(b*NCH + chunk)*DIN + e)*NSz + n;
    Pc[idx] = P;
    Hc[idx] = h;
}

__global__ void scan_chunk_prefix(const float* __restrict__ Pc, const float* __restrict__ Hc,
                                  float* __restrict__ Hin, int NCH) {
    int i = blockIdx.x*blockDim.x + threadIdx.x;
    int b = i / (DIN*NSz);
    int inner = i % (DIN*NSz);
    float h = 0.f;
    for (int c = 0; c < NCH; c++) {
        size_t idx = (size_t)(b*NCH + c)*(DIN*NSz) + inner;
        Hin[idx] = h;
        h = fmaf(Pc[idx], h, Hc[idx]);
    }
}

__global__ void scan_chunk_final(const float* __restrict__ dt, const float* __restrict__ xi,
                                 const float* __restrict__ proj, const float* __restrict__ xz,
                                 const float* __restrict__ A_log, const float* __restrict__ Dskip,
                                 const float* __restrict__ Hin, float* __restrict__ y,
                                 int L, int NCH) {
    int b  = blockIdx.x / (DIN/8);
    int ch = blockIdx.x % (DIN/8);
    int chunk = blockIdx.y;
    int e = ch*8 + (threadIdx.x >> 4);
    int n = threadIdx.x & 15;
    float A  = -expf(A_log[e*NSz + n]);
    float Dk = Dskip[e];
    size_t sidx = ((size_t)(b*NCH + chunk)*DIN + e)*NSz + n;
    float h = Hin[sidx];
    int l0 = chunk*64;
    int lend = min(l0 + 64, L);
    size_t base_de = (size_t)b*L*DIN + e;
    size_t base_p  = (size_t)b*L*44;
    size_t base_z  = (size_t)b*L*(2*DIN) + DIN + e;
    for (int l = l0; l < lend; l++) {
        float tdt = dt[base_de + (size_t)l*DIN];
        float txi = xi[base_de + (size_t)l*DIN];
        float tB  = proj[base_p + (size_t)l*44 + DTRz + n];
        float tC  = proj[base_p + (size_t)l*44 + DTRz + NSz + n];
        float dA = __expf(tdt * A);
        h = fmaf(dA, h, tdt*txi*tB);
        float p = h * tC;
        p += __shfl_xor_sync(0xffffffffu, p, 8);
        p += __shfl_xor_sync(0xffffffffu, p, 4);
        p += __shfl_xor_sync(0xffffffffu, p, 2);
        p += __shfl_xor_sync(0xffffffffu, p, 1);
        if (n == 0) {
            float zv = xz[base_z + (size_t)l*(2*DIN)];
            float sz = zv / (1.f + __expf(-zv));
            y[base_de + (size_t)l*DIN] = (p + Dk*txi) * sz;
        }
    }
}

// ---------------- transpose (B,L,192)->(B,192,L), add or assign ----------------
__global__ void add_transpose(const float* __restrict__ src, float* __restrict__ dst,
                              int L, int mode) {
    __shared__ float s[32][33];
    int b  = blockIdx.z;
    int d0 = blockIdx.y * 32;
    int l0 = blockIdx.x * 32;
    int tx = threadIdx.x, ty = threadIdx.y;
    #pragma unroll
    for (int i = 0; i < 32; i += 8) {
        int l = l0 + ty + i, d = d0 + tx;
        if (l < L) s[ty+i][tx] = src[((size_t)b*L + l)*Dm + d];
    }
    __syncthreads();
    #pragma unroll
    for (int i = 0; i < 32; i += 8) {
        int d = d0 + ty + i, l = l0 + tx;
        if (l < L) {
            size_t o = ((size_t)b*Dm + d)*L + l;
            float v = s[tx][ty+i];
            if (mode) dst[o] = v; else dst[o] += v;
        }
    }
}

// ---------------- 2x2 maxpool ----------------
__global__ void maxpool2(const float* __restrict__ in, float* __restrict__ out) {
    int i = blockIdx.x*blockDim.x + threadIdx.x;
    if (i >= Bz*Dm*28*28) return;
    int wo = i % 28, ho = (i/28) % 28;
    int d = (i/784) % Dm, b = i/(784*Dm);
    const float* p = in + (((size_t)(b*Dm + d)*56 + 2*ho)*56 + 2*wo);
    out[i] = fmaxf(fmaxf(p[0], p[1]), fmaxf(p[56], p[57]));
}

// ---------------- host ----------------
extern "C" void kernel_launch(void* const* d_in, const int* in_sizes, int n_in,
                              void* d_out, int out_size) {
    const float* x      = (const float*)d_in[0];
    const float* proj_w = (const float*)d_in[1];
    const float* proj_b = (const float*)d_in[2];
    const float* bn_g   = (const float*)d_in[3];
    const float* bn_b   = (const float*)d_in[4];
    const float* bn_mean= (const float*)d_in[5];
    const float* bn_var = (const float*)d_in[6];
    const float* ln_g   = (const float*)d_in[7];
    const float* ln_b   = (const float*)d_in[8];
    const float* Win    = (const float*)d_in[9];
    const float* b_in   = (const float*)d_in[10];
    const float* conv_w = (const float*)d_in[11];
    const float* conv_b = (const float*)d_in[12];
    const float* Wx     = (const float*)d_in[13];
    const float* Wdt    = (const float*)d_in[14];
    const float* bdt    = (const float*)d_in[15];
    const float* A_log  = (const float*)d_in[16];
    const float* Dskip  = (const float*)d_in[17];
    const float* Wout   = (const float*)d_in[18];
    const float* bout   = (const float*)d_in[19];
    float* out = (float*)d_out;

    float *px, *ppool, *ph, *pxz, *pxi, *pproj, *pdt, *py, *pblk, *pPc, *pHc, *pHin;
    cudaGetSymbolAddress((void**)&px,    g_x);
    cudaGetSymbolAddress((void**)&ppool, g_pool);
    cudaGetSymbolAddress((void**)&ph,    g_h);
    cudaGetSymbolAddress((void**)&pxz,   g_xz);
    cudaGetSymbolAddress((void**)&pxi,   g_xi);
    cudaGetSymbolAddress((void**)&pproj, g_proj);
    cudaGetSymbolAddress((void**)&pdt,   g_dt);
    cudaGetSymbolAddress((void**)&py,    g_y);
    cudaGetSymbolAddress((void**)&pblk,  g_blk);
    cudaGetSymbolAddress((void**)&pPc,   g_Pc);
    cudaGetSymbolAddress((void**)&pHc,   g_Hc);
    cudaGetSymbolAddress((void**)&pHin,  g_Hin);

    // stem: 1x1 conv + BN
    proj_bn_kernel<<<Bz*(Dm/8)*4, 256>>>(x, proj_w, proj_b, bn_g, bn_b, bn_mean, bn_var, px);

    auto run_block = [&](int i, const float* xin, int L, float* dst, int mode) {
        int BLc = Bz * L;
        int NCH = (L + 63) / 64;
        int tiles = (L + 31) / 32;
        int mtiles = (BLc + 127) / 128;
        ln_kernel<<<Bz*tiles, 256>>>(xin, ln_g + i*Dm, ln_b + i*Dm, ph, L);

        // in-proj: (BLc x 192) * (768 x 192)^T
        bgemm<<<dim3((2*DIN)/64, mtiles), 256>>>(
            ph, Dm, Win + (size_t)i*2*DIN*Dm, Dm,
            b_in + i*2*DIN, pxz, 2*DIN, BLc, 2*DIN, Dm, 0);

        conv_silu<<<BLc, DIN>>>(pxz, conv_w + i*DIN*KC, conv_b + i*DIN, pxi, L);

        // x-proj: (BLc x 384) * (44 x 384)^T
        bgemm<<<dim3(1, mtiles), 256>>>(
            pxi, DIN, Wx + (size_t)i*44*DIN, DIN,
            nullptr, pproj, 44, BLc, 44, DIN, 0);

        // dt-proj + softplus: (BLc x 12) * (384 x 12)^T
        bgemm<<<dim3(DIN/64, mtiles), 256>>>(
            pproj, 44, Wdt + (size_t)i*DIN*DTRz, DTRz,
            bdt + i*DIN, pdt, DIN, BLc, DIN, DTRz, 1);

        dim3 gsc(Bz*(DIN/8), NCH);
        scan_chunk_local<<<gsc, 128>>>(pdt, pxi, pproj,
                                       A_log + (size_t)i*DIN*NSz, pPc, pHc, L, NCH);
        scan_chunk_prefix<<<(Bz*DIN*NSz)/256, 256>>>(pPc, pHc, pHin, NCH);
        scan_chunk_final<<<gsc, 128>>>(pdt, pxi, pproj, pxz,
                                       A_log + (size_t)i*DIN*NSz, Dskip + i*DIN,
                                       pHin, py, L, NCH);

        // out-proj: (BLc x 384) * (192 x 384)^T
        bgemm<<<dim3(Dm/64, mtiles), 256>>>(
            py, DIN, Wout + (size_t)i*Dm*DIN, DIN,
            bout + i*Dm, pblk, Dm, BLc, Dm, DIN, 0);

        dim3 gtr((L + 31)/32, Dm/32, Bz);
        add_transpose<<<gtr, dim3(32, 8)>>>(pblk, dst, L, mode);
    };

    run_block(0, px, L0z, px, 0);      // x = x + blk0(x)
    run_block(1, px, L0z, px, 0);      // x = x + blk1(x)

    // skip = x  (second output region)
    cudaMemcpyAsync(out + (size_t)Bz*Dm*L1z, px, sizeof(float)*(size_t)Bz*Dm*L0z,
                    cudaMemcpyDeviceToDevice);

    maxpool2<<<(Bz*Dm*784 + 255)/256, 256>>>(px, ppool);
    run_block(2, ppool, L1z, out, 1);  // x_final = blk2(pool(x)) -> first output region
}

// round 12
// speedup vs baseline: 9.5561x; 1.0540x over previous
#include <cuda_runtime.h>
#include <cuda_bf16.h>
#include <cstdint>

#define Dm   192
#define DIN  384
#define NSz  16
#define DTRz 12
#define KC   4
#define CIN  96
#define Bz   2
#define L0z  3136
#define L1z  784
#define BL0  (Bz*L0z)
#define NCHMAX 49
#define ASTR 40   // smem row stride in bf16 elements (conflict-free)

// ---------------- static scratch (no allocs allowed) ----------------
__device__ float g_x   [Bz*L0z*Dm];      // activation (B, L, D)
__device__ float g_pool[Bz*L1z*Dm];      // maxpooled (B, L1, D)
__device__ float g_h   [BL0*Dm];         // xT for stem, then layernorm output (B*L, D)
__device__ float g_xz  [BL0*2*DIN];
__device__ float g_xi  [BL0*DIN];
__device__ float g_proj[BL0*44];
__device__ float g_dt  [BL0*DIN];
__device__ float g_y   [BL0*DIN];
__device__ float g_blk [BL0*Dm];
__device__ float g_Pc  [Bz*NCHMAX*DIN*NSz];
__device__ float g_Hc  [Bz*NCHMAX*DIN*NSz];
__device__ float g_Hin [Bz*NCHMAX*DIN*NSz];
__device__ float g_w2  [Dm*CIN];         // BN-folded stem weight
__device__ float g_b2  [Dm];             // BN-folded stem bias

#define MMA_BF16(c, a, b)                                                     \
    asm volatile("mma.sync.aligned.m16n8k16.row.col.f32.bf16.bf16.f32 "       \
        "{%0,%1,%2,%3},{%4,%5,%6,%7},{%8,%9},{%0,%1,%2,%3};"                  \
        : "+f"((c)[0]), "+f"((c)[1]), "+f"((c)[2]), "+f"((c)[3])              \
        : "r"((a)[0]), "r"((a)[1]), "r"((a)[2]), "r"((a)[3]),                 \
          "r"((b)[0]), "r"((b)[1]))

__device__ __forceinline__ uint32_t pack2(__nv_bfloat16 a, __nv_bfloat16 b) {
    return (uint32_t)__bfloat16_as_ushort(a) | ((uint32_t)__bfloat16_as_ushort(b) << 16);
}
__device__ __forceinline__ void split2(float x, float y, uint32_t& hi, uint32_t& lo) {
    __nv_bfloat16 hx = __float2bfloat16(x), hy = __float2bfloat16(y);
    __nv_bfloat16 lx = __float2bfloat16(x - __bfloat162float(hx));
    __nv_bfloat16 ly = __float2bfloat16(y - __bfloat162float(hy));
    hi = pack2(hx, hy);
    lo = pack2(lx, ly);
}

// ============ bf16x3 tensor-core GEMM: C = A(M,K)*B(N,K)^T + bias ============
// BM=128, BN template (64/128), BK=32, 256 threads, 8 warps as 2m x 4n.
// 3-term split: AhBh + AlBh + AhBl. addC: C += result (residual fusion).
template<int BN>
__global__ __launch_bounds__(256) void bgemm(
        const float* __restrict__ A, int lda,
        const float* __restrict__ B, int ldb,
        const float* __restrict__ bias,
        float* __restrict__ C, int ldc,
        int M, int N, int K, int act, int addC) {
    constexpr int J = BN / 32;     // n-blocks per warp; also B staging iters
    __shared__ __align__(16) uint16_t sAh[128*ASTR];
    __shared__ __align__(16) uint16_t sAl[128*ASTR];
    __shared__ __align__(16) uint16_t sBh[BN*ASTR];
    __shared__ __align__(16) uint16_t sBl[BN*ASTR];

    int bm = blockIdx.y * 128, bn = blockIdx.x * BN;
    int tid  = threadIdx.x;
    int lane = tid & 31;
    int w    = tid >> 5;
    int m0 = (w & 1) * 64;
    int n0 = (w >> 1) * (BN/4);
    int gq = lane >> 2;
    int tq = lane & 3;

    float c[4][J][4];
    #pragma unroll
    for (int i = 0; i < 4; i++)
        #pragma unroll
        for (int j = 0; j < J; j++)
            #pragma unroll
            for (int t = 0; t < 4; t++) c[i][j][t] = 0.f;

    float4 pa[4], pb[J];
    const float4 z4 = make_float4(0.f,0.f,0.f,0.f);

    auto ldA = [&](int k0) {
        #pragma unroll
        for (int it = 0; it < 4; it++) {
            int idx = tid + it*256;
            int r = idx >> 3, q = idx & 7;
            int gm = bm + r, gk = k0 + q*4;
            pa[it] = (gm < M && gk < K) ? *(const float4*)(A + (size_t)gm*lda + gk) : z4;
        }
    };
    auto ldB = [&](int k0) {
        #pragma unroll
        for (int it = 0; it < J; it++) {
            int idx = tid + it*256;
            int r = idx >> 3, q = idx & 7;
            int gn = bn + r, gk = k0 + q*4;
            pb[it] = (gn < N && gk < K) ? *(const float4*)(B + (size_t)gn*ldb + gk) : z4;
        }
    };
    auto stA = [&]() {
        #pragma unroll
        for (int it = 0; it < 4; it++) {
            int idx = tid + it*256;
            int r = idx >> 3, q = idx & 7;
            uint32_t h0, l0, h1, l1;
            split2(pa[it].x, pa[it].y, h0, l0);
            split2(pa[it].z, pa[it].w, h1, l1);
            int off = r*ASTR + q*4;
            *(uint2*)(sAh + off) = make_uint2(h0, h1);
            *(uint2*)(sAl + off) = make_uint2(l0, l1);
        }
    };
    auto stB = [&]() {
        #pragma unroll
        for (int it = 0; it < J; it++) {
            int idx = tid + it*256;
            int r = idx >> 3, q = idx & 7;
            uint32_t h0, l0, h1, l1;
            split2(pb[it].x, pb[it].y, h0, l0);
            split2(pb[it].z, pb[it].w, h1, l1);
            int off = r*ASTR + q*4;
            *(uint2*)(sBh + off) = make_uint2(h0, h1);
            *(uint2*)(sBl + off) = make_uint2(l0, l1);
        }
    };

    int nst = (K + 31) / 32;
    ldA(0); ldB(0);
    for (int s = 0; s < nst; s++) {
        stA(); stB();
        __syncthreads();
        if (s + 1 < nst) { ldA((s+1)*32); ldB((s+1)*32); }

        #pragma unroll
        for (int ks = 0; ks < 32; ks += 16) {
            uint32_t ah[4][4], al[4][4], bh[J][2], bl[J][2];
            #pragma unroll
            for (int i = 0; i < 4; i++) {
                int mb = m0 + i*16 + gq;
                int o0 = mb*ASTR + 2*tq + ks;
                int o1 = (mb+8)*ASTR + 2*tq + ks;
                ah[i][0] = *(const uint32_t*)(sAh + o0);
                ah[i][1] = *(const uint32_t*)(sAh + o1);
                ah[i][2] = *(const uint32_t*)(sAh + o0 + 8);
                ah[i][3] = *(const uint32_t*)(sAh + o1 + 8);
                al[i][0] = *(const uint32_t*)(sAl + o0);
                al[i][1] = *(const uint32_t*)(sAl + o1);
                al[i][2] = *(const uint32_t*)(sAl + o0 + 8);
                al[i][3] = *(const uint32_t*)(sAl + o1 + 8);
            }
            #pragma unroll
            for (int j = 0; j < J; j++) {
                int nb = n0 + j*8 + gq;
                int o = nb*ASTR + 2*tq + ks;
                bh[j][0] = *(const uint32_t*)(sBh + o);
                bh[j][1] = *(const uint32_t*)(sBh + o + 8);
                bl[j][0] = *(const uint32_t*)(sBl + o);
                bl[j][1] = *(const uint32_t*)(sBl + o + 8);
            }
            #pragma unroll
            for (int i = 0; i < 4; i++)
                #pragma unroll
                for (int j = 0; j < J; j++) {
                    MMA_BF16(c[i][j], ah[i], bh[j]);
                    MMA_BF16(c[i][j], al[i], bh[j]);
                    MMA_BF16(c[i][j], ah[i], bl[j]);
                }
        }
        __syncthreads();
    }

    // ---- epilogue ----
    #pragma unroll
    for (int i = 0; i < 4; i++) {
        #pragma unroll
        for (int j = 0; j < J; j++) {
            int n = bn + n0 + j*8 + tq*2;
            if (n >= N) continue;
            float b0 = bias ? bias[n]   : 0.f;
            float b1 = bias ? bias[n+1] : 0.f;
            #pragma unroll
            for (int hh = 0; hh < 2; hh++) {
                int gm = bm + m0 + i*16 + gq + hh*8;
                if (gm >= M) continue;
                float v0 = c[i][j][hh*2 + 0] + b0;
                float v1 = c[i][j][hh*2 + 1] + b1;
                float* cp = C + (size_t)gm*ldc + n;
                if (addC) {
                    float2 old = *(float2*)cp;
                    v0 += old.x; v1 += old.y;
                } else if (act == 1) {
                    v0 = (v0 > 20.f) ? v0 : log1pf(__expf(v0));
                    v1 = (v1 > 20.f) ? v1 : log1pf(__expf(v1));
                }
                *(float2*)cp = make_float2(v0, v1);
            }
        }
    }
}

// ---------------- transpose (B,D,L)->(B,L,D), generic D (mult of 32) --------
__global__ void transpose_dl(const float* __restrict__ src, float* __restrict__ dst,
                             int L, int D) {
    __shared__ float s[32][33];
    int b  = blockIdx.z;
    int d0 = blockIdx.y * 32;
    int l0 = blockIdx.x * 32;
    int tx = threadIdx.x, ty = threadIdx.y;
    #pragma unroll
    for (int i = 0; i < 32; i += 8) {
        int d = d0 + ty + i, l = l0 + tx;
        if (l < L) s[ty+i][tx] = src[((size_t)b*D + d)*L + l];
    }
    __syncthreads();
    #pragma unroll
    for (int i = 0; i < 32; i += 8) {
        int l = l0 + ty + i, d = d0 + tx;
        if (l < L) dst[((size_t)b*L + l)*D + d] = s[tx][ty+i];
    }
}

// ---------------- transpose (B,L,Dm)->(B,Dm,L) (for outputs) ----------------
__global__ void transpose_ld(const float* __restrict__ src, float* __restrict__ dst,
                             int L) {
    __shared__ float s[32][33];
    int b  = blockIdx.z;
    int d0 = blockIdx.y * 32;
    int l0 = blockIdx.x * 32;
    int tx = threadIdx.x, ty = threadIdx.y;
    #pragma unroll
    for (int i = 0; i < 32; i += 8) {
        int l = l0 + ty + i, d = d0 + tx;
        if (l < L) s[ty+i][tx] = src[((size_t)b*L + l)*Dm + d];
    }
    __syncthreads();
    #pragma unroll
    for (int i = 0; i < 32; i += 8) {
        int d = d0 + ty + i, l = l0 + tx;
        if (l < L) dst[((size_t)b*Dm + d)*L + l] = s[tx][ty+i];
    }
}

// ---------------- fold BN into stem weights ----------------
__global__ void wprep(const float* __restrict__ w, const float* __restrict__ pb,
                      const float* __restrict__ bg, const float* __restrict__ bb,
                      const float* __restrict__ bm, const float* __restrict__ bv,
                      float* __restrict__ w2, float* __restrict__ b2) {
    int idx = blockIdx.x*256 + threadIdx.x;
    if (idx >= Dm*CIN) return;
    int o = idx / CIN, c = idx % CIN;
    float sc = rsqrtf(bv[o] + 1e-5f) * bg[o];
    w2[idx] = w[idx] * sc;
    if (c == 0) b2[o] = bb[o] - bm[o]*sc + pb[o]*sc;
}

// ---------------- row LayerNorm over D=192 on (B*L, D) ----------------
__global__ void ln_row(const float* __restrict__ xin, const float* __restrict__ g,
                       const float* __restrict__ bb, float* __restrict__ hout) {
    int warp = threadIdx.x >> 5, lane = threadIdx.x & 31;
    int row = blockIdx.x*8 + warp;
    const float* xr = xin + (size_t)row*Dm;
    float v[6]; float sum = 0.f, sq = 0.f;
    #pragma unroll
    for (int j = 0; j < 6; j++) { v[j] = xr[lane + 32*j]; sum += v[j]; sq += v[j]*v[j]; }
    #pragma unroll
    for (int o = 16; o > 0; o >>= 1) {
        sum += __shfl_xor_sync(0xffffffffu, sum, o);
        sq  += __shfl_xor_sync(0xffffffffu, sq,  o);
    }
    float mu = sum * (1.f/Dm);
    float var = sq * (1.f/Dm) - mu*mu;
    float rs = rsqrtf(var + 1e-5f);
    float* orow = hout + (size_t)row*Dm;
    #pragma unroll
    for (int j = 0; j < 6; j++) {
        int cidx = lane + 32*j;
        orow[cidx] = (v[j]-mu)*rs*g[cidx] + bb[cidx];
    }
}

// ---------------- causal depthwise conv (K=4) + SiLU, smem-tiled ------------
__global__ __launch_bounds__(384) void conv_silu2(const float* __restrict__ xz,
                                                  const float* __restrict__ w,
                                                  const float* __restrict__ cb,
                                                  float* __restrict__ xo, int L) {
    __shared__ float sx[19*384];
    int ntile = L / 16;
    int b  = blockIdx.x / ntile;
    int l0 = (blockIdx.x % ntile) * 16;
    for (int idx = threadIdx.x; idx < 19*384; idx += 384) {
        int r = idx / 384, e = idx % 384;
        int l = l0 - 3 + r;
        sx[idx] = (l >= 0) ? xz[((size_t)b*L + l)*(2*DIN) + e] : 0.f;
    }
    __syncthreads();
    int e = threadIdx.x;
    float4 wv = *(const float4*)(w + e*4);
    float cbe = cb[e];
    #pragma unroll 4
    for (int li = 0; li < 16; li++) {
        float acc = cbe;
        acc = fmaf(sx[(li+0)*384 + e], wv.x, acc);
        acc = fmaf(sx[(li+1)*384 + e], wv.y, acc);
        acc = fmaf(sx[(li+2)*384 + e], wv.z, acc);
        acc = fmaf(sx[(li+3)*384 + e], wv.w, acc);
        float sg = 1.f / (1.f + __expf(-acc));
        xo[((size_t)b*L + l0 + li)*DIN + e] = acc * sg;
    }
}

// ---------------- chunked selective scan (unchanged, proven) ----------------
__global__ void scan_chunk_local(const float* __restrict__ dt, const float* __restrict__ xi,
                                 const float* __restrict__ proj, const float* __restrict__ A_log,
                                 float* __restrict__ Pc, float* __restrict__ Hc,
                                 int L, int NCH) {
    int b  = blockIdx.x / (DIN/8);
    int ch = blockIdx.x % (DIN/8);
    int chunk = blockIdx.y;
    int e = ch*8 + (threadIdx.x >> 4);
    int n = threadIdx.x & 15;
    float A = -expf(A_log[e*NSz + n]);
    float h = 0.f, P = 1.f;
    int l0 = chunk*64;
    int lend = min(l0 + 64, L);
    size_t base_de = (size_t)b*L*DIN + e;
    size_t base_p  = (size_t)b*L*44 + DTRz + n;
    for (int l = l0; l < lend; l++) {
        float tdt = dt[base_de + (size_t)l*DIN];
        float txi = xi[base_de + (size_t)l*DIN];
        float tB  = proj[base_p + (size_t)l*44];
        float dA = __expf(tdt * A);
        h = fmaf(dA, h, tdt*txi*tB);
        P *= dA;
    }
    size_t idx = ((size_t)(b*NCH + chunk)*DIN + e)*NSz + n;
    Pc[idx] = P;
    Hc[idx] = h;
}

__global__ void scan_chunk_prefix(const float* __restrict__ Pc, const float* __restrict__ Hc,
                                  float* __restrict__ Hin, int NCH) {
    int i = blockIdx.x*blockDim.x + threadIdx.x;
    int b = i / (DIN*NSz);
    int inner = i % (DIN*NSz);
    float h = 0.f;
    for (int c = 0; c < NCH; c++) {
        size_t idx = (size_t)(b*NCH + c)*(DIN*NSz) + inner;
        Hin[idx] = h;
        h = fmaf(Pc[idx], h, Hc[idx]);
    }
}

__global__ void scan_chunk_final(const float* __restrict__ dt, const float* __restrict__ xi,
                                 const float* __restrict__ proj, const float* __restrict__ xz,
                                 const float* __restrict__ A_log, const float* __restrict__ Dskip,
                                 const float* __restrict__ Hin, float* __restrict__ y,
                                 int L, int NCH) {
    int b  = blockIdx.x / (DIN/8);
    int ch = blockIdx.x % (DIN/8);
    int chunk = blockIdx.y;
    int e = ch*8 + (threadIdx.x >> 4);
    int n = threadIdx.x & 15;
    float A  = -expf(A_log[e*NSz + n]);
    float Dk = Dskip[e];
    size_t sidx = ((size_t)(b*NCH + chunk)*DIN + e)*NSz + n;
    float h = Hin[sidx];
    int l0 = chunk*64;
    int lend = min(l0 + 64, L);
    size_t base_de = (size_t)b*L*DIN + e;
    size_t base_p  = (size_t)b*L*44;
    size_t base_z  = (size_t)b*L*(2*DIN) + DIN + e;
    for (int l = l0; l < lend; l++) {
        float tdt = dt[base_de + (size_t)l*DIN];
        float txi = xi[base_de + (size_t)l*DIN];
        float tB  = proj[base_p + (size_t)l*44 + DTRz + n];
        float tC  = proj[base_p + (size_t)l*44 + DTRz + NSz + n];
        float dA = __expf(tdt * A);
        h = fmaf(dA, h, tdt*txi*tB);
        float p = h * tC;
        p += __shfl_xor_sync(0xffffffffu, p, 8);
        p += __shfl_xor_sync(0xffffffffu, p, 4);
        p += __shfl_xor_sync(0xffffffffu, p, 2);
        p += __shfl_xor_sync(0xffffffffu, p, 1);
        if (n == 0) {
            float zv = xz[base_z + (size_t)l*(2*DIN)];
            float sz = zv / (1.f + __expf(-zv));
            y[base_de + (size_t)l*DIN] = (p + Dk*txi) * sz;
        }
    }
}

// ---------------- 2x2 maxpool on (B,L,D) ----------------
__global__ void maxpool2(const float* __restrict__ in, float* __restrict__ out) {
    int i = blockIdx.x*blockDim.x + threadIdx.x;
    if (i >= Bz*L1z*Dm) return;
    int d = i % Dm;
    int l = (i / Dm) % L1z;
    int b = i / (Dm * L1z);
    int ho = l / 28, wo = l % 28;
    size_t base = ((size_t)b*L0z + (2*ho)*56 + 2*wo)*Dm + d;
    float v = fmaxf(fmaxf(in[base], in[base + Dm]),
                    fmaxf(in[base + 56*Dm], in[base + 57*Dm]));
    out[i] = v;
}

// ---------------- host ----------------
extern "C" void kernel_launch(void* const* d_in, const int* in_sizes, int n_in,
                              void* d_out, int out_size) {
    const float* x      = (const float*)d_in[0];
    const float* proj_w = (const float*)d_in[1];
    const float* proj_b = (const float*)d_in[2];
    const float* bn_g   = (const float*)d_in[3];
    const float* bn_b   = (const float*)d_in[4];
    const float* bn_mean= (const float*)d_in[5];
    const float* bn_var = (const float*)d_in[6];
    const float* ln_g   = (const float*)d_in[7];
    const float* ln_b   = (const float*)d_in[8];
    const float* Win    = (const float*)d_in[9];
    const float* b_in   = (const float*)d_in[10];
    const float* conv_w = (const float*)d_in[11];
    const float* conv_b = (const float*)d_in[12];
    const float* Wx     = (const float*)d_in[13];
    const float* Wdt    = (const float*)d_in[14];
    const float* bdt    = (const float*)d_in[15];
    const float* A_log  = (const float*)d_in[16];
    const float* Dskip  = (const float*)d_in[17];
    const float* Wout   = (const float*)d_in[18];
    const float* bout   = (const float*)d_in[19];
    float* out = (float*)d_out;

    float *px, *ppool, *ph, *pxz, *pxi, *pproj, *pdt, *py, *pblk, *pPc, *pHc, *pHin, *pw2, *pb2;
    cudaGetSymbolAddress((void**)&px,    g_x);
    cudaGetSymbolAddress((void**)&ppool, g_pool);
    cudaGetSymbolAddress((void**)&ph,    g_h);
    cudaGetSymbolAddress((void**)&pxz,   g_xz);
    cudaGetSymbolAddress((void**)&pxi,   g_xi);
    cudaGetSymbolAddress((void**)&pproj, g_proj);
    cudaGetSymbolAddress((void**)&pdt,   g_dt);
    cudaGetSymbolAddress((void**)&py,    g_y);
    cudaGetSymbolAddress((void**)&pblk,  g_blk);
    cudaGetSymbolAddress((void**)&pPc,   g_Pc);
    cudaGetSymbolAddress((void**)&pHc,   g_Hc);
    cudaGetSymbolAddress((void**)&pHin,  g_Hin);
    cudaGetSymbolAddress((void**)&pw2,   g_w2);
    cudaGetSymbolAddress((void**)&pb2,   g_b2);

    // ---- stem: transpose x to (B,L,96), fold BN into weights, GEMM -> px (B,L,192)
    transpose_dl<<<dim3(L0z/32, CIN/32, Bz), dim3(32,8)>>>(x, ph, L0z, CIN);
    wprep<<<(Dm*CIN + 255)/256, 256>>>(proj_w, proj_b, bn_g, bn_b, bn_mean, bn_var, pw2, pb2);
    bgemm<64><<<dim3(Dm/64, (BL0+127)/128), 256>>>(
        ph, CIN, pw2, CIN, pb2, px, Dm, BL0, Dm, CIN, 0, 0);

    auto run_block = [&](int i, const float* xin, int L, float* dst, int addC) {
        int BLc = Bz * L;
        int NCH = (L + 63) / 64;
        int mtiles = (BLc + 127) / 128;

        ln_row<<<BLc/8, 256>>>(xin, ln_g + i*Dm, ln_b + i*Dm, ph);

        // in-proj: (BLc x 192) * (768 x 192)^T  [BN=128]
        bgemm<128><<<dim3((2*DIN)/128, mtiles), 256>>>(
            ph, Dm, Win + (size_t)i*2*DIN*Dm, Dm,
            b_in + i*2*DIN, pxz, 2*DIN, BLc, 2*DIN, Dm, 0, 0);

        conv_silu2<<<Bz*(L/16), 384>>>(pxz, conv_w + i*DIN*KC, conv_b + i*DIN, pxi, L);

        // x-proj: (BLc x 384) * (44 x 384)^T  [BN=64]
        bgemm<64><<<dim3(1, mtiles), 256>>>(
            pxi, DIN, Wx + (size_t)i*44*DIN, DIN,
            nullptr, pproj, 44, BLc, 44, DIN, 0, 0);

        // dt-proj + softplus: (BLc x 12) * (384 x 12)^T  [BN=64]
        bgemm<64><<<dim3(DIN/64, mtiles), 256>>>(
            pproj, 44, Wdt + (size_t)i*DIN*DTRz, DTRz,
            bdt + i*DIN, pdt, DIN, BLc, DIN, DTRz, 1, 0);

        dim3 gsc(Bz*(DIN/8), NCH);
        scan_chunk_local<<<gsc, 128>>>(pdt, pxi, pproj,
                                       A_log + (size_t)i*DIN*NSz, pPc, pHc, L, NCH);
        scan_chunk_prefix<<<(Bz*DIN*NSz)/256, 256>>>(pPc, pHc, pHin, NCH);
        scan_chunk_final<<<gsc, 128>>>(pdt, pxi, pproj, pxz,
                                       A_log + (size_t)i*DIN*NSz, Dskip + i*DIN,
                                       pHin, py, L, NCH);

        // out-proj: (BLc x 384) * (192 x 384)^T  [BN=64], residual fused via addC
        bgemm<64><<<dim3(Dm/64, mtiles), 256>>>(
            py, DIN, Wout + (size_t)i*Dm*DIN, DIN,
            bout + i*Dm, dst, Dm, BLc, Dm, DIN, 0, addC);
    };

    run_block(0, px, L0z, px, 1);      // x += blk0(x)   (in-place residual)
    run_block(1, px, L0z, px, 1);      // x += blk1(x)

    // skip output: (B,L0,D) -> (B,D,L0) into out's second region
    transpose_ld<<<dim3(L0z/32, Dm/32, Bz), dim3(32,8)>>>(px, out + (size_t)Bz*Dm*L1z, L0z);

    maxpool2<<<(Bz*L1z*Dm + 255)/256, 256>>>(px, ppool);
    run_block(2, ppool, L1z, pblk, 0); // pblk = blk2(pool(x)) in (B,L1,D)

    // final output: (B,L1,D) -> (B,D,L1) into out's first region
    transpose_ld<<<dim3((L1z+31)/32, Dm/32, Bz), dim3(32,8)>>>(pblk, out, L1z);
}